// round 1
// baseline (speedup 1.0000x reference)
#include <cuda_runtime.h>

#define NN 50000
#define EE 600000
#define HH 128
#define MIDD 256

typedef unsigned long long u64;

// ---- scratch (device globals: no allocation allowed) ----
__device__ float g_agg1[NN * HH];
__device__ float g_agg2[NN * HH];
__device__ float g_agg3[NN * HH];

// ---- packed f32x2 helpers (sm_100+ PTX) ----
__device__ __forceinline__ u64 dup2(float x) {
    u64 r; asm("mov.b64 %0, {%1, %1};" : "=l"(r) : "f"(x)); return r;
}
__device__ __forceinline__ void fma2(u64 &d, u64 a, u64 b) {
    asm("fma.rn.f32x2 %0, %1, %2, %0;" : "+l"(d) : "l"(a), "l"(b));
}
__device__ __forceinline__ float2 unpk(u64 v) {
    float2 r; asm("mov.b64 {%0, %1}, %2;" : "=f"(r.x), "=f"(r.y) : "l"(v)); return r;
}

// ============================================================================
// Edge MLP + gather + scatter:
//   f = relu(feat @ Wa + ba) @ Wb + bb          (feat: [E, DK], Wa: [DK,256], Wb: [256,128])
//   agg[dst[e]] += f[e] * x[src[e]]             (atomic scatter-add)
// Block = 64 edges, 256 threads (16x16), thread tile 4e x 8h.
// Mid (256) processed in 4 chunks of 64 staged through smem.
// ============================================================================
template<int DK>
__global__ __launch_bounds__(256, 2) void edge_mlp_scatter(
    const float* __restrict__ feat,
    const float* __restrict__ Wa, const float* __restrict__ ba,
    const float* __restrict__ Wb, const float* __restrict__ bb,
    const float* __restrict__ x, const int* __restrict__ eidx,
    float* __restrict__ agg)
{
    extern __shared__ float sm[];
    float* sFt  = sm;                       // [DK][68]  feat tile, k-major
    float* sW   = sm + DK * 68;             // 8192 floats (W chunk, reused)
    float* sMt  = sW + 8192;                // [64][68]  mid chunk, m-major
    int*   sIdx = (int*)(sMt + 64 * 68);    // [128] src(0..63), dst(64..127)

    const int tid = threadIdx.x;
    const int tx = tid & 15, ty = tid >> 4;
    const int e0 = blockIdx.x * 64;

    if (tid < 128) {
        int e = tid & 63;
        sIdx[tid] = (tid < 64) ? eidx[e0 + e] : eidx[EE + e0 + e];
    }

    // load feat tile transposed (coalesced global float4, scattered smem writes)
    constexpr int DK4 = DK / 4;
    for (int i4 = tid; i4 < 64 * DK4; i4 += 256) {
        int e = i4 / DK4, k4 = i4 % DK4;
        float4 v = *(const float4*)(feat + (size_t)(e0 + e) * DK + k4 * 4);
        sFt[(k4 * 4 + 0) * 68 + e] = v.x;
        sFt[(k4 * 4 + 1) * 68 + e] = v.y;
        sFt[(k4 * 4 + 2) * 68 + e] = v.z;
        sFt[(k4 * 4 + 3) * 68 + e] = v.w;
    }

    u64 acc2[4][4];
    #pragma unroll
    for (int i = 0; i < 4; i++)
        #pragma unroll
        for (int j = 0; j < 4; j++) acc2[i][j] = 0ull;

    for (int mc = 0; mc < 4; mc++) {
        __syncthreads();
        // load Wa chunk [DK][64]   (Wa row stride = 256)
        for (int i4 = tid; i4 < DK * 16; i4 += 256) {
            int k = i4 >> 4, c4 = i4 & 15;
            *(float4*)(sW + k * 64 + c4 * 4) =
                *(const float4*)(Wa + (size_t)k * MIDD + mc * 64 + c4 * 4);
        }
        __syncthreads();

        // GEMM1: mid[64e][64c] = featT @ WaChunk
        u64 acc1[4][2];
        #pragma unroll
        for (int i = 0; i < 4; i++) { acc1[i][0] = 0ull; acc1[i][1] = 0ull; }
        #pragma unroll 4
        for (int k = 0; k < DK; k++) {
            float4 a = *(const float4*)(sFt + k * 68 + ty * 4);
            const ulonglong2 b = *(const ulonglong2*)(sW + k * 64 + tx * 4);
            u64 a0 = dup2(a.x), a1 = dup2(a.y), a2 = dup2(a.z), a3 = dup2(a.w);
            fma2(acc1[0][0], a0, b.x); fma2(acc1[0][1], a0, b.y);
            fma2(acc1[1][0], a1, b.x); fma2(acc1[1][1], a1, b.y);
            fma2(acc1[2][0], a2, b.x); fma2(acc1[2][1], a2, b.y);
            fma2(acc1[3][0], a3, b.x); fma2(acc1[3][1], a3, b.y);
        }
        __syncthreads();

        // relu(mid + ba) -> sMt (m-major), and load Wb chunk [64][128]
        #pragma unroll
        for (int i = 0; i < 4; i++) {
            #pragma unroll
            for (int p = 0; p < 2; p++) {
                float2 v = unpk(acc1[i][p]);
                int c = tx * 4 + p * 2;
                sMt[(c + 0) * 68 + ty * 4 + i] = fmaxf(v.x + ba[mc * 64 + c + 0], 0.f);
                sMt[(c + 1) * 68 + ty * 4 + i] = fmaxf(v.y + ba[mc * 64 + c + 1], 0.f);
            }
        }
        for (int i4 = tid; i4 < 64 * 32; i4 += 256) {
            int m = i4 >> 5, h4 = i4 & 31;
            *(float4*)(sW + m * 128 + h4 * 4) =
                *(const float4*)(Wb + (size_t)(mc * 64 + m) * HH + h4 * 4);
        }
        __syncthreads();

        // GEMM2: out[64e][128h] += midChunk @ WbChunk
        #pragma unroll 4
        for (int m = 0; m < 64; m++) {
            float4 a = *(const float4*)(sMt + m * 68 + ty * 4);
            const ulonglong2 b01 = *(const ulonglong2*)(sW + m * 128 + tx * 8);
            const ulonglong2 b23 = *(const ulonglong2*)(sW + m * 128 + tx * 8 + 4);
            u64 a0 = dup2(a.x), a1 = dup2(a.y), a2 = dup2(a.z), a3 = dup2(a.w);
            fma2(acc2[0][0], a0, b01.x); fma2(acc2[0][1], a0, b01.y);
            fma2(acc2[0][2], a0, b23.x); fma2(acc2[0][3], a0, b23.y);
            fma2(acc2[1][0], a1, b01.x); fma2(acc2[1][1], a1, b01.y);
            fma2(acc2[1][2], a1, b23.x); fma2(acc2[1][3], a1, b23.y);
            fma2(acc2[2][0], a2, b01.x); fma2(acc2[2][1], a2, b01.y);
            fma2(acc2[2][2], a2, b23.x); fma2(acc2[2][3], a2, b23.y);
            fma2(acc2[3][0], a3, b01.x); fma2(acc2[3][1], a3, b01.y);
            fma2(acc2[3][2], a3, b23.x); fma2(acc2[3][3], a3, b23.y);
        }
    }
    __syncthreads();

    // gather x[src] into smem (reuse sFt/sW region), stride 132
    float* sXJ = sm;
    for (int i4 = tid; i4 < 64 * 32; i4 += 256) {
        int e = i4 >> 5, h4 = i4 & 31;
        int s = sIdx[e];
        *(float4*)(sXJ + e * 132 + h4 * 4) =
            *(const float4*)(x + (size_t)s * HH + h4 * 4);
    }
    __syncthreads();

    float bbv[8];
    #pragma unroll
    for (int j = 0; j < 8; j++) bbv[j] = bb[tx * 8 + j];

    #pragma unroll
    for (int i = 0; i < 4; i++) {
        int e = ty * 4 + i;
        int d = sIdx[64 + e];
        float* dp = agg + (size_t)d * HH + tx * 8;
        const float4 u0 = *(const float4*)(sXJ + e * 132 + tx * 8);
        const float4 u1 = *(const float4*)(sXJ + e * 132 + tx * 8 + 4);
        float2 c0 = unpk(acc2[i][0]), c1 = unpk(acc2[i][1]);
        float2 c2 = unpk(acc2[i][2]), c3 = unpk(acc2[i][3]);
        atomicAdd(dp + 0, (c0.x + bbv[0]) * u0.x);
        atomicAdd(dp + 1, (c0.y + bbv[1]) * u0.y);
        atomicAdd(dp + 2, (c1.x + bbv[2]) * u0.z);
        atomicAdd(dp + 3, (c1.y + bbv[3]) * u0.w);
        atomicAdd(dp + 4, (c2.x + bbv[4]) * u1.x);
        atomicAdd(dp + 5, (c2.y + bbv[5]) * u1.y);
        atomicAdd(dp + 6, (c3.x + bbv[6]) * u1.z);
        atomicAdd(dp + 7, (c3.y + bbv[7]) * u1.w);
    }
}

// ============================================================================
// GINE scatter: agg3[d2[e]] += x[s2[e]] + edge_attr[e].  Warp per edge.
// ============================================================================
__global__ __launch_bounds__(256) void gine_scatter(
    const float* __restrict__ x, const float* __restrict__ ea,
    const int* __restrict__ eidx, float* __restrict__ agg3)
{
    int e = blockIdx.x * 8 + (threadIdx.x >> 5);
    int lane = threadIdx.x & 31;
    int s = eidx[e];
    int d = eidx[EE + e];
    float4 v  = *(const float4*)(ea + (size_t)e * HH + lane * 4);
    float4 xv = *(const float4*)(x  + (size_t)s * HH + lane * 4);
    float* dp = agg3 + (size_t)d * HH + lane * 4;
    atomicAdd(dp + 0, v.x + xv.x);
    atomicAdd(dp + 1, v.y + xv.y);
    atomicAdd(dp + 2, v.z + xv.z);
    atomicAdd(dp + 3, v.w + xv.w);
}

// ============================================================================
// Node-level fused: h1, h2, cat-GEMM, GINE MLP (+LayerNorm), final sum.
// Block = 64 nodes, 256 threads (16x16), thread tile 4n x 8h.
// ============================================================================
__global__ __launch_bounds__(256, 1) void node_fused(
    const float* __restrict__ x,
    const float* __restrict__ W1_rel, const float* __restrict__ b1_rel,
    const float* __restrict__ W1_root,
    const float* __restrict__ W2_rel, const float* __restrict__ b2_rel,
    const float* __restrict__ W2_root,
    const float* __restrict__ Wc, const float* __restrict__ bc,
    const float* __restrict__ epsp,
    const float* __restrict__ Wg1, const float* __restrict__ bg1,
    const float* __restrict__ lng, const float* __restrict__ lnb,
    const float* __restrict__ Wg2, const float* __restrict__ bg2,
    float* __restrict__ out)
{
    extern __shared__ float sm[];
    float* sXT = sm;               // [128][68] x tile (later g tile), k-major
    float* sA  = sm + 8704;        // [128][68] agg tile (reused 1,2,3)
    float* sT1 = sm + 17408;       // [128][68] h1 / normed-t, k-major
    float* sT2 = sm + 26112;       // [128][68] h2 ; later h (linear [64][132])
    float* sW  = sm + 34816;       // [128][128] weight

    const int tid = threadIdx.x;
    const int tx = tid & 15, ty = tid >> 4;
    const int n0 = blockIdx.x * 64;

    auto loadT = [&](float* dst, const float* src) {
        for (int i4 = tid; i4 < 64 * 32; i4 += 256) {
            int n = i4 >> 5, h4 = i4 & 31;
            int row = n0 + n;
            float4 v = make_float4(0.f, 0.f, 0.f, 0.f);
            if (row < NN) v = *(const float4*)(src + (size_t)row * HH + h4 * 4);
            dst[(h4 * 4 + 0) * 68 + n] = v.x;
            dst[(h4 * 4 + 1) * 68 + n] = v.y;
            dst[(h4 * 4 + 2) * 68 + n] = v.z;
            dst[(h4 * 4 + 3) * 68 + n] = v.w;
        }
    };
    auto loadW = [&](const float* W) {
        for (int i4 = tid; i4 < 4096; i4 += 256)
            *(float4*)(sW + i4 * 4) = *(const float4*)(W + i4 * 4);
    };
    auto gemm = [&](const float* A, u64 acc[4][4]) {
        #pragma unroll 4
        for (int k = 0; k < 128; k++) {
            float4 a = *(const float4*)(A + k * 68 + ty * 4);
            const ulonglong2 b01 = *(const ulonglong2*)(sW + k * 128 + tx * 8);
            const ulonglong2 b23 = *(const ulonglong2*)(sW + k * 128 + tx * 8 + 4);
            u64 a0 = dup2(a.x), a1 = dup2(a.y), a2 = dup2(a.z), a3 = dup2(a.w);
            fma2(acc[0][0], a0, b01.x); fma2(acc[0][1], a0, b01.y);
            fma2(acc[0][2], a0, b23.x); fma2(acc[0][3], a0, b23.y);
            fma2(acc[1][0], a1, b01.x); fma2(acc[1][1], a1, b01.y);
            fma2(acc[1][2], a1, b23.x); fma2(acc[1][3], a1, b23.y);
            fma2(acc[2][0], a2, b01.x); fma2(acc[2][1], a2, b01.y);
            fma2(acc[2][2], a2, b23.x); fma2(acc[2][3], a2, b23.y);
            fma2(acc[3][0], a3, b01.x); fma2(acc[3][1], a3, b01.y);
            fma2(acc[3][2], a3, b23.x); fma2(acc[3][3], a3, b23.y);
        }
    };
    auto zacc = [&](u64 acc[4][4]) {
        #pragma unroll
        for (int i = 0; i < 4; i++)
            #pragma unroll
            for (int j = 0; j < 4; j++) acc[i][j] = 0ull;
    };
    auto unpack_bias_relu = [&](u64 acc[4][4], const float* bptr, float v[4][8]) {
        float bias[8];
        #pragma unroll
        for (int j = 0; j < 8; j++) bias[j] = bptr[tx * 8 + j];
        #pragma unroll
        for (int i = 0; i < 4; i++)
            #pragma unroll
            for (int p = 0; p < 4; p++) {
                float2 c = unpk(acc[i][p]);
                v[i][2 * p + 0] = fmaxf(c.x + bias[2 * p + 0], 0.f);
                v[i][2 * p + 1] = fmaxf(c.y + bias[2 * p + 1], 0.f);
            }
    };
    auto storeT = [&](float* dst, float v[4][8]) {
        #pragma unroll
        for (int i = 0; i < 4; i++)
            #pragma unroll
            for (int j = 0; j < 8; j++)
                dst[(tx * 8 + j) * 68 + ty * 4 + i] = v[i][j];
    };

    u64 acc[4][4];
    float v[4][8];

    loadT(sXT, x);
    loadT(sA, g_agg1);
    zacc(acc);
    __syncthreads();
    loadW(W1_rel); __syncthreads();
    gemm(sA, acc);
    __syncthreads(); loadW(W1_root); __syncthreads();
    gemm(sXT, acc);
    unpack_bias_relu(acc, b1_rel, v);
    storeT(sT1, v);                      // h1

    loadT(sA, g_agg2);
    zacc(acc);
    __syncthreads();
    loadW(W2_rel); __syncthreads();
    gemm(sA, acc);
    __syncthreads(); loadW(W2_root); __syncthreads();
    gemm(sXT, acc);
    unpack_bias_relu(acc, b2_rel, v);
    storeT(sT2, v);                      // h2

    zacc(acc);
    __syncthreads();
    loadW(Wc); __syncthreads();          // Wc rows 0..127 (h1 half)
    gemm(sT1, acc);
    __syncthreads(); loadW(Wc + 128 * 128); __syncthreads();
    gemm(sT2, acc);
    unpack_bias_relu(acc, bc, v);        // v = h
    __syncthreads();                     // all readers of sT2 done
    #pragma unroll
    for (int i = 0; i < 4; i++)
        #pragma unroll
        for (int j = 0; j < 8; j++)
            sT2[(ty * 4 + i) * 132 + tx * 8 + j] = v[i][j];   // h, linear

    loadT(sA, g_agg3);
    __syncthreads();
    float epsv = 1.0f + *epsp;
    for (int idx = tid; idx < 8192; idx += 256) {
        int k = idx >> 6, n = idx & 63;
        sXT[k * 68 + n] = sXT[k * 68 + n] * epsv + sA[k * 68 + n];   // g
    }

    zacc(acc);
    __syncthreads();
    loadW(Wg1); __syncthreads();
    gemm(sXT, acc);                      // t = g @ Wg1

    // + bg1, LayerNorm over h (half-warp shfl reduce), affine, relu
    {
        float bias[8], lgv[8], lbv[8];
        #pragma unroll
        for (int j = 0; j < 8; j++) {
            bias[j] = bg1[tx * 8 + j];
            lgv[j] = lng[tx * 8 + j];
            lbv[j] = lnb[tx * 8 + j];
        }
        float tv[4][8];
        #pragma unroll
        for (int i = 0; i < 4; i++)
            #pragma unroll
            for (int p = 0; p < 4; p++) {
                float2 c = unpk(acc[i][p]);
                tv[i][2 * p + 0] = c.x + bias[2 * p + 0];
                tv[i][2 * p + 1] = c.y + bias[2 * p + 1];
            }
        #pragma unroll
        for (int i = 0; i < 4; i++) {
            float s = 0.f, s2 = 0.f;
            #pragma unroll
            for (int j = 0; j < 8; j++) { s += tv[i][j]; s2 += tv[i][j] * tv[i][j]; }
            #pragma unroll
            for (int d = 1; d < 16; d <<= 1) {
                s  += __shfl_xor_sync(0xffffffffu, s, d);
                s2 += __shfl_xor_sync(0xffffffffu, s2, d);
            }
            float mean = s * (1.0f / 128.0f);
            float var  = s2 * (1.0f / 128.0f) - mean * mean;
            float rstd = rsqrtf(var + 1e-5f);
            #pragma unroll
            for (int j = 0; j < 8; j++) {
                float val = (tv[i][j] - mean) * rstd * lgv[j] + lbv[j];
                v[i][j] = fmaxf(val, 0.f);
            }
        }
    }
    storeT(sT1, v);                      // relu(LN(t))

    zacc(acc);
    __syncthreads();
    loadW(Wg2); __syncthreads();
    gemm(sT1, acc);                      // h3 pre-bias

    {
        float bias[8];
        #pragma unroll
        for (int j = 0; j < 8; j++) bias[j] = bg2[tx * 8 + j];
        #pragma unroll
        for (int i = 0; i < 4; i++) {
            int row = n0 + ty * 4 + i;
            if (row >= NN) continue;
            float o[8];
            #pragma unroll
            for (int p = 0; p < 4; p++) {
                float2 c = unpk(acc[i][p]);
                o[2 * p + 0] = c.x + bias[2 * p + 0];
                o[2 * p + 1] = c.y + bias[2 * p + 1];
            }
            const float* hrow = sT2 + (ty * 4 + i) * 132 + tx * 8;
            float4 o0 = make_float4(o[0] + hrow[0], o[1] + hrow[1],
                                    o[2] + hrow[2], o[3] + hrow[3]);
            float4 o1 = make_float4(o[4] + hrow[4], o[5] + hrow[5],
                                    o[6] + hrow[6], o[7] + hrow[7]);
            *(float4*)(out + (size_t)row * HH + tx * 8)     = o0;
            *(float4*)(out + (size_t)row * HH + tx * 8 + 4) = o1;
        }
    }
}

// ============================================================================
// Launch
// ============================================================================
extern "C" void kernel_launch(void* const* d_in, const int* in_sizes, int n_in,
                              void* d_out, int out_size)
{
    const float* x        = (const float*)d_in[0];
    const float* feature1 = (const float*)d_in[1];
    const float* feature2 = (const float*)d_in[2];
    const int *pei, *ei;
    const float* ea;
    if (in_sizes[3] == 2 * EE) {           // signature order
        pei = (const int*)d_in[3]; ei = (const int*)d_in[4];
        ea  = (const float*)d_in[5];
    } else {                               // setup_inputs dict order
        ea  = (const float*)d_in[3];
        pei = (const int*)d_in[4]; ei = (const int*)d_in[5];
    }
    const float* Wf1a   = (const float*)d_in[6];
    const float* bf1a   = (const float*)d_in[7];
    const float* Wf1b   = (const float*)d_in[8];
    const float* bf1b   = (const float*)d_in[9];
    const float* Wf2a   = (const float*)d_in[10];
    const float* bf2a   = (const float*)d_in[11];
    const float* Wf2b   = (const float*)d_in[12];
    const float* bf2b   = (const float*)d_in[13];
    const float* W1_rel = (const float*)d_in[14];
    const float* b1_rel = (const float*)d_in[15];
    const float* W1_root= (const float*)d_in[16];
    const float* W2_rel = (const float*)d_in[17];
    const float* b2_rel = (const float*)d_in[18];
    const float* W2_root= (const float*)d_in[19];
    const float* epsp   = (const float*)d_in[20];
    const float* Wg1    = (const float*)d_in[21];
    const float* bg1    = (const float*)d_in[22];
    const float* lng    = (const float*)d_in[23];
    const float* lnb    = (const float*)d_in[24];
    const float* Wg2    = (const float*)d_in[25];
    const float* bg2    = (const float*)d_in[26];
    const float* Wc     = (const float*)d_in[27];
    const float* bc     = (const float*)d_in[28];
    float* out = (float*)d_out;

    float *agg1, *agg2, *agg3;
    cudaGetSymbolAddress((void**)&agg1, g_agg1);
    cudaGetSymbolAddress((void**)&agg2, g_agg2);
    cudaGetSymbolAddress((void**)&agg3, g_agg3);

    cudaFuncSetAttribute(edge_mlp_scatter<128>,
                         cudaFuncAttributeMaxDynamicSharedMemorySize, 85504);
    cudaFuncSetAttribute(edge_mlp_scatter<32>,
                         cudaFuncAttributeMaxDynamicSharedMemorySize, 59392);
    cudaFuncSetAttribute(node_fused,
                         cudaFuncAttributeMaxDynamicSharedMemorySize, 204800);

    cudaMemsetAsync(agg1, 0, sizeof(float) * NN * HH);
    cudaMemsetAsync(agg2, 0, sizeof(float) * NN * HH);
    cudaMemsetAsync(agg3, 0, sizeof(float) * NN * HH);

    edge_mlp_scatter<128><<<EE / 64, 256, 85504>>>(
        feature1, Wf1a, bf1a, Wf1b, bf1b, x, pei, agg1);
    edge_mlp_scatter<32><<<EE / 64, 256, 59392>>>(
        feature2, Wf2a, bf2a, Wf2b, bf2b, x, pei, agg2);
    gine_scatter<<<EE / 8, 256>>>(x, ea, ei, agg3);

    node_fused<<<(NN + 63) / 64, 256, 204800>>>(
        x, W1_rel, b1_rel, W1_root, W2_rel, b2_rel, W2_root,
        Wc, bc, epsp, Wg1, bg1, lng, lnb, Wg2, bg2, out);
}

// round 3
// speedup vs baseline: 2.8663x; 2.8663x over previous
#include <cuda_runtime.h>
#include <cuda_fp16.h>

#define NN 50000
#define EE 600000
#define HH 128
#define MIDD 256

typedef unsigned int u32;
typedef unsigned long long u64;

// ---------------- scratch (device globals) ----------------
__device__ float g_agg1[NN * HH];
__device__ float g_agg2[NN * HH];
__device__ float g_agg3[NN * HH];

// transposed padded fp16 weight images: [n][k] rows, padded strides
__device__ __align__(16) __half g_W1aT[256 * 136];  // Wf1a^T  (k=128, stride 136)
__device__ __align__(16) __half g_W2aT[128 * 264];  // Wf1b^T  (k=256, stride 264)
__device__ __align__(16) __half g_W1bT[256 * 40];   // Wf2a^T  (k=32,  stride 40)
__device__ __align__(16) __half g_W2bT[128 * 264];  // Wf2b^T  (k=256, stride 264)

// ---------------- helpers ----------------
__device__ __forceinline__ u32 cvta_smem(const void* p) {
    u32 a;
    asm("{ .reg .u64 t; cvta.to.shared.u64 t, %1; cvt.u32.u64 %0, t; }"
        : "=r"(a) : "l"(p));
    return a;
}
__device__ __forceinline__ void ldm4(u32 r[4], u32 addr) {
    asm volatile("ldmatrix.sync.aligned.m8n8.x4.shared.b16 {%0,%1,%2,%3}, [%4];"
        : "=r"(r[0]), "=r"(r[1]), "=r"(r[2]), "=r"(r[3]) : "r"(addr));
}
__device__ __forceinline__ void mma16816(float c[4], const u32 a[4], u32 b0, u32 b1) {
    asm volatile(
        "mma.sync.aligned.m16n8k16.row.col.f32.f16.f16.f32 "
        "{%0,%1,%2,%3}, {%4,%5,%6,%7}, {%8,%9}, {%0,%1,%2,%3};"
        : "+f"(c[0]), "+f"(c[1]), "+f"(c[2]), "+f"(c[3])
        : "r"(a[0]), "r"(a[1]), "r"(a[2]), "r"(a[3]), "r"(b0), "r"(b1));
}
__device__ __forceinline__ u32 pack2(float x, float y) {
    __half2 h = __floats2half2_rn(x, y);
    return *(u32*)&h;
}
__device__ __forceinline__ void red4(float* p, float a, float b, float c, float d) {
    asm volatile("red.global.add.v4.f32 [%0], {%1, %2, %3, %4};"
                 :: "l"(p), "f"(a), "f"(b), "f"(c), "f"(d) : "memory");
}

// ---- packed f32x2 helpers (node_fused) ----
__device__ __forceinline__ u64 dup2(float x) {
    u64 r; asm("mov.b64 %0, {%1, %1};" : "=l"(r) : "f"(x)); return r;
}
__device__ __forceinline__ void fma2(u64 &d, u64 a, u64 b) {
    asm("fma.rn.f32x2 %0, %1, %2, %0;" : "+l"(d) : "l"(a), "l"(b));
}
__device__ __forceinline__ float2 unpk(u64 v) {
    float2 r; asm("mov.b64 {%0, %1}, %2;" : "=f"(r.x), "=f"(r.y) : "l"(v)); return r;
}

// ============================================================================
// Weight prep: transpose + fp16 convert into padded [n][k] images.
// ============================================================================
__global__ void prep_weights(const float* __restrict__ Wf1a,
                             const float* __restrict__ Wf1b,
                             const float* __restrict__ Wf2a,
                             const float* __restrict__ Wf2b)
{
    int tid = blockIdx.x * blockDim.x + threadIdx.x;
    int nt = gridDim.x * blockDim.x;
    for (int i = tid; i < 256 * 128; i += nt) {      // W1aT [256n][128k]
        int n = i >> 7, k = i & 127;
        g_W1aT[n * 136 + k] = __float2half(Wf1a[k * 256 + n]);
    }
    for (int i = tid; i < 128 * 256; i += nt) {      // W2aT / W2bT [128n][256k]
        int n = i >> 8, k = i & 255;
        g_W2aT[n * 264 + k] = __float2half(Wf1b[k * 128 + n]);
        g_W2bT[n * 264 + k] = __float2half(Wf2b[k * 128 + n]);
    }
    for (int i = tid; i < 256 * 32; i += nt) {       // W1bT [256n][32k]
        int n = i >> 5, k = i & 31;
        g_W1bT[n * 40 + k] = __float2half(Wf2a[k * 256 + n]);
    }
}

// ============================================================================
// Edge MLP via HMMA (mma.sync m16n8k16 fp16->f32):
//   mid = relu(feat @ Wa + ba)   [128e, 256]
//   f   = mid @ Wb               [128e, 128]   (bb added at scatter)
//   agg[dst] += (f + bb) * x[src]
// Block: 256 thr = 8 warps, 128 edges/tile, 4 tiles/block (grid 1172).
// ============================================================================
template<int DK>
__global__ __launch_bounds__(256, 1) void edge_hmma(
    const float* __restrict__ feat,
    const float* __restrict__ ba, const float* __restrict__ bb,
    const float* __restrict__ x, const int* __restrict__ eidx,
    float* __restrict__ agg,
    const __half* __restrict__ W1T, const __half* __restrict__ W2T)
{
    constexpr int SW1 = DK + 8;                 // halfs
    constexpr int W1SZ = 256 * SW1 * 2;         // bytes
    constexpr int SW2 = 264;
    constexpr int W2SZ = 128 * SW2 * 2;
    constexpr int SA = DK + 8;
    constexpr int ASZ = 128 * SA * 2;
    constexpr int SF = 136;
    constexpr int OW1 = 0;
    constexpr int OW2 = OW1 + W1SZ;
    constexpr int OA  = OW2 + W2SZ;
    constexpr int OF  = OA + ASZ;
    constexpr int OBA = OF + 128 * SF * 2;
    constexpr int OBB = OBA + 1024;
    constexpr int OSRC = OBB + 512;
    constexpr int ODST = OSRC + 512;
    constexpr int NKT = DK / 16;

    extern __shared__ unsigned char smraw[];
    const u32 sb = cvta_smem(smraw);
    const int tid = threadIdx.x;
    const int w = tid >> 5, lane = tid & 31;
    int* sSrc = (int*)(smraw + OSRC);
    int* sDst = (int*)(smraw + ODST);
    float* sBa = (float*)(smraw + OBA);
    float* sBb = (float*)(smraw + OBB);

    // stage weights + biases
    {
        const uint4* w1 = (const uint4*)W1T;
        const uint4* w2 = (const uint4*)W2T;
        uint4* s1 = (uint4*)(smraw + OW1);
        uint4* s2 = (uint4*)(smraw + OW2);
        for (int i = tid; i < W1SZ / 16; i += 256) s1[i] = w1[i];
        for (int i = tid; i < W2SZ / 16; i += 256) s2[i] = w2[i];
        sBa[tid] = ba[tid];
        if (tid < 128) sBb[tid] = bb[tid];
    }

    for (int t = 0; t < 4; t++) {
        const int e0 = (blockIdx.x * 4 + t) * 128;
        __syncthreads();   // protect smem reuse across tiles
        if (tid < 128) {
            int e = e0 + tid;
            sSrc[tid] = (e < EE) ? eidx[e] : 0;
            sDst[tid] = (e < EE) ? eidx[EE + e] : 0;
        }
        // feat -> fp16 smem [128][SA]
        constexpr int DK4 = DK / 4;
        for (int i = tid; i < 128 * DK4; i += 256) {
            int e = i / DK4, k4 = i % DK4;
            float4 v = make_float4(0.f, 0.f, 0.f, 0.f);
            if (e0 + e < EE) v = *(const float4*)(feat + (size_t)(e0 + e) * DK + k4 * 4);
            __half* dst = (__half*)(smraw + OA) + e * SA + k4 * 4;
            *(u32*)(dst)     = pack2(v.x, v.y);
            *(u32*)(dst + 2) = pack2(v.z, v.w);
        }
        __syncthreads();

        // --- A1 fragments (feat rows of this warp) ---
        u32 a1[NKT][4];
        #pragma unroll
        for (int kt = 0; kt < NKT; kt++)
            ldm4(a1[kt], sb + OA + ((16 * w + (lane & 15)) * SA + kt * 16 + ((lane >> 4) << 3)) * 2);

        float acc2[16][4];
        #pragma unroll
        for (int j = 0; j < 16; j++)
            #pragma unroll
            for (int q = 0; q < 4; q++) acc2[j][q] = 0.f;

        #pragma unroll
        for (int nc = 0; nc < 4; nc++) {         // 64 mid-cols per chunk
            float acc1[8][4];
            #pragma unroll
            for (int j = 0; j < 8; j++)
                #pragma unroll
                for (int q = 0; q < 4; q++) acc1[j][q] = 0.f;

            #pragma unroll
            for (int kt = 0; kt < NKT; kt++) {
                #pragma unroll
                for (int nn = 0; nn < 4; nn++) { // 16 n each -> 2 n8 tiles
                    u32 b[4];
                    ldm4(b, sb + OW1 + ((nc * 64 + nn * 16 + (lane & 7) + ((lane >> 4) << 3)) * SW1
                                        + kt * 16 + (((lane >> 3) & 1) << 3)) * 2);
                    mma16816(acc1[2 * nn],     a1[kt], b[0], b[1]);
                    mma16816(acc1[2 * nn + 1], a1[kt], b[2], b[3]);
                }
            }
            // bias + relu + pack into GEMM2 A fragments (4 k16 tiles)
            u32 a2[4][4];
            #pragma unroll
            for (int tt = 0; tt < 4; tt++) {
                int c0 = nc * 64 + tt * 16 + 2 * (lane & 3);
                float b0 = sBa[c0], b1 = sBa[c0 + 1];
                float b8 = sBa[c0 + 8], b9 = sBa[c0 + 9];
                a2[tt][0] = pack2(fmaxf(acc1[2 * tt][0] + b0, 0.f),
                                  fmaxf(acc1[2 * tt][1] + b1, 0.f));
                a2[tt][1] = pack2(fmaxf(acc1[2 * tt][2] + b0, 0.f),
                                  fmaxf(acc1[2 * tt][3] + b1, 0.f));
                a2[tt][2] = pack2(fmaxf(acc1[2 * tt + 1][0] + b8, 0.f),
                                  fmaxf(acc1[2 * tt + 1][1] + b9, 0.f));
                a2[tt][3] = pack2(fmaxf(acc1[2 * tt + 1][2] + b8, 0.f),
                                  fmaxf(acc1[2 * tt + 1][3] + b9, 0.f));
            }
            // GEMM2 partial: acc2 += a2 @ W2[kchunk]
            #pragma unroll
            for (int tt = 0; tt < 4; tt++) {
                #pragma unroll
                for (int nn = 0; nn < 8; nn++) {
                    u32 b[4];
                    ldm4(b, sb + OW2 + ((nn * 16 + (lane & 7) + ((lane >> 4) << 3)) * SW2
                                        + nc * 64 + tt * 16 + (((lane >> 3) & 1) << 3)) * 2);
                    mma16816(acc2[2 * nn],     a2[tt], b[0], b[1]);
                    mma16816(acc2[2 * nn + 1], a2[tt], b[2], b[3]);
                }
            }
        }

        // store f to smem fp16 [128][SF]
        {
            __half* F = (__half*)(smraw + OF);
            int row = 16 * w + (lane >> 2);
            #pragma unroll
            for (int j = 0; j < 16; j++) {
                int col = j * 8 + 2 * (lane & 3);
                *(u32*)(F + row * SF + col)       = pack2(acc2[j][0], acc2[j][1]);
                *(u32*)(F + (row + 8) * SF + col) = pack2(acc2[j][2], acc2[j][3]);
            }
        }
        __syncthreads();

        // scatter: 2 threads per edge, 64 cols each
        {
            int e = tid >> 1;
            int ch = (tid & 1) * 64;
            if (e0 + e < EE) {
                int src = sSrc[e], dst = sDst[e];
                const __half* Fr = (const __half*)(smraw + OF) + e * SF + ch;
                const float4* xr = (const float4*)(x + (size_t)src * HH + ch);
                const float4* bbp = (const float4*)(sBb + ch);
                float* ap = agg + (size_t)dst * HH + ch;
                #pragma unroll
                for (int q = 0; q < 16; q++) {
                    float4 xv = __ldg(xr + q);
                    float4 bv = bbp[q];
                    float2 f0 = __half22float2(*(const __half2*)(Fr + q * 4));
                    float2 f1 = __half22float2(*(const __half2*)(Fr + q * 4 + 2));
                    red4(ap + q * 4,
                         (f0.x + bv.x) * xv.x, (f0.y + bv.y) * xv.y,
                         (f1.x + bv.z) * xv.z, (f1.y + bv.w) * xv.w);
                }
            }
        }
    }
}

// ============================================================================
// GINE scatter: agg3[d2[e]] += x[s2[e]] + edge_attr[e].  Warp per edge, red.v4.
// ============================================================================
__global__ __launch_bounds__(256) void gine_scatter(
    const float* __restrict__ x, const float* __restrict__ ea,
    const int* __restrict__ eidx, float* __restrict__ agg3)
{
    int e = blockIdx.x * 8 + (threadIdx.x >> 5);
    int lane = threadIdx.x & 31;
    int s = eidx[e];
    int d = eidx[EE + e];
    float4 v  = *(const float4*)(ea + (size_t)e * HH + lane * 4);
    float4 xv = *(const float4*)(x  + (size_t)s * HH + lane * 4);
    red4(agg3 + (size_t)d * HH + lane * 4, v.x + xv.x, v.y + xv.y, v.z + xv.z, v.w + xv.w);
}

// ============================================================================
// Node-level fused: h1, h2, cat-GEMM, GINE MLP (+LayerNorm), final sum.
// ============================================================================
__global__ __launch_bounds__(256, 1) void node_fused(
    const float* __restrict__ x,
    const float* __restrict__ W1_rel, const float* __restrict__ b1_rel,
    const float* __restrict__ W1_root,
    const float* __restrict__ W2_rel, const float* __restrict__ b2_rel,
    const float* __restrict__ W2_root,
    const float* __restrict__ Wc, const float* __restrict__ bc,
    const float* __restrict__ epsp,
    const float* __restrict__ Wg1, const float* __restrict__ bg1,
    const float* __restrict__ lng, const float* __restrict__ lnb,
    const float* __restrict__ Wg2, const float* __restrict__ bg2,
    float* __restrict__ out)
{
    extern __shared__ float sm[];
    float* sXT = sm;
    float* sA  = sm + 8704;
    float* sT1 = sm + 17408;
    float* sT2 = sm + 26112;
    float* sW  = sm + 34816;

    const int tid = threadIdx.x;
    const int tx = tid & 15, ty = tid >> 4;
    const int n0 = blockIdx.x * 64;

    auto loadT = [&](float* dst, const float* src) {
        for (int i4 = tid; i4 < 64 * 32; i4 += 256) {
            int n = i4 >> 5, h4 = i4 & 31;
            int row = n0 + n;
            float4 v = make_float4(0.f, 0.f, 0.f, 0.f);
            if (row < NN) v = *(const float4*)(src + (size_t)row * HH + h4 * 4);
            dst[(h4 * 4 + 0) * 68 + n] = v.x;
            dst[(h4 * 4 + 1) * 68 + n] = v.y;
            dst[(h4 * 4 + 2) * 68 + n] = v.z;
            dst[(h4 * 4 + 3) * 68 + n] = v.w;
        }
    };
    auto loadW = [&](const float* W) {
        for (int i4 = tid; i4 < 4096; i4 += 256)
            *(float4*)(sW + i4 * 4) = *(const float4*)(W + i4 * 4);
    };
    auto gemm = [&](const float* A, u64 acc[4][4]) {
        #pragma unroll 4
        for (int k = 0; k < 128; k++) {
            float4 a = *(const float4*)(A + k * 68 + ty * 4);
            const ulonglong2 b01 = *(const ulonglong2*)(sW + k * 128 + tx * 8);
            const ulonglong2 b23 = *(const ulonglong2*)(sW + k * 128 + tx * 8 + 4);
            u64 a0 = dup2(a.x), a1 = dup2(a.y), a2 = dup2(a.z), a3 = dup2(a.w);
            fma2(acc[0][0], a0, b01.x); fma2(acc[0][1], a0, b01.y);
            fma2(acc[0][2], a0, b23.x); fma2(acc[0][3], a0, b23.y);
            fma2(acc[1][0], a1, b01.x); fma2(acc[1][1], a1, b01.y);
            fma2(acc[1][2], a1, b23.x); fma2(acc[1][3], a1, b23.y);
            fma2(acc[2][0], a2, b01.x); fma2(acc[2][1], a2, b01.y);
            fma2(acc[2][2], a2, b23.x); fma2(acc[2][3], a2, b23.y);
            fma2(acc[3][0], a3, b01.x); fma2(acc[3][1], a3, b01.y);
            fma2(acc[3][2], a3, b23.x); fma2(acc[3][3], a3, b23.y);
        }
    };
    auto zacc = [&](u64 acc[4][4]) {
        #pragma unroll
        for (int i = 0; i < 4; i++)
            #pragma unroll
            for (int j = 0; j < 4; j++) acc[i][j] = 0ull;
    };
    auto unpack_bias_relu = [&](u64 acc[4][4], const float* bptr, float v[4][8]) {
        float bias[8];
        #pragma unroll
        for (int j = 0; j < 8; j++) bias[j] = bptr[tx * 8 + j];
        #pragma unroll
        for (int i = 0; i < 4; i++)
            #pragma unroll
            for (int p = 0; p < 4; p++) {
                float2 c = unpk(acc[i][p]);
                v[i][2 * p + 0] = fmaxf(c.x + bias[2 * p + 0], 0.f);
                v[i][2 * p + 1] = fmaxf(c.y + bias[2 * p + 1], 0.f);
            }
    };
    auto storeT = [&](float* dst, float v[4][8]) {
        #pragma unroll
        for (int i = 0; i < 4; i++)
            #pragma unroll
            for (int j = 0; j < 8; j++)
                dst[(tx * 8 + j) * 68 + ty * 4 + i] = v[i][j];
    };

    u64 acc[4][4];
    float v[4][8];

    loadT(sXT, x);
    loadT(sA, g_agg1);
    zacc(acc);
    __syncthreads();
    loadW(W1_rel); __syncthreads();
    gemm(sA, acc);
    __syncthreads(); loadW(W1_root); __syncthreads();
    gemm(sXT, acc);
    unpack_bias_relu(acc, b1_rel, v);
    storeT(sT1, v);

    loadT(sA, g_agg2);
    zacc(acc);
    __syncthreads();
    loadW(W2_rel); __syncthreads();
    gemm(sA, acc);
    __syncthreads(); loadW(W2_root); __syncthreads();
    gemm(sXT, acc);
    unpack_bias_relu(acc, b2_rel, v);
    storeT(sT2, v);

    zacc(acc);
    __syncthreads();
    loadW(Wc); __syncthreads();
    gemm(sT1, acc);
    __syncthreads(); loadW(Wc + 128 * 128); __syncthreads();
    gemm(sT2, acc);
    unpack_bias_relu(acc, bc, v);
    __syncthreads();
    #pragma unroll
    for (int i = 0; i < 4; i++)
        #pragma unroll
        for (int j = 0; j < 8; j++)
            sT2[(ty * 4 + i) * 132 + tx * 8 + j] = v[i][j];

    loadT(sA, g_agg3);
    __syncthreads();
    float epsv = 1.0f + *epsp;
    for (int idx = tid; idx < 8192; idx += 256) {
        int k = idx >> 6, n = idx & 63;
        sXT[k * 68 + n] = sXT[k * 68 + n] * epsv + sA[k * 68 + n];
    }

    zacc(acc);
    __syncthreads();
    loadW(Wg1); __syncthreads();
    gemm(sXT, acc);

    {
        float bias[8], lgv[8], lbv[8];
        #pragma unroll
        for (int j = 0; j < 8; j++) {
            bias[j] = bg1[tx * 8 + j];
            lgv[j] = lng[tx * 8 + j];
            lbv[j] = lnb[tx * 8 + j];
        }
        float tv[4][8];
        #pragma unroll
        for (int i = 0; i < 4; i++)
            #pragma unroll
            for (int p = 0; p < 4; p++) {
                float2 c = unpk(acc[i][p]);
                tv[i][2 * p + 0] = c.x + bias[2 * p + 0];
                tv[i][2 * p + 1] = c.y + bias[2 * p + 1];
            }
        #pragma unroll
        for (int i = 0; i < 4; i++) {
            float s = 0.f, s2 = 0.f;
            #pragma unroll
            for (int j = 0; j < 8; j++) { s += tv[i][j]; s2 += tv[i][j] * tv[i][j]; }
            #pragma unroll
            for (int d = 1; d < 16; d <<= 1) {
                s  += __shfl_xor_sync(0xffffffffu, s, d);
                s2 += __shfl_xor_sync(0xffffffffu, s2, d);
            }
            float mean = s * (1.0f / 128.0f);
            float var  = s2 * (1.0f / 128.0f) - mean * mean;
            float rstd = rsqrtf(var + 1e-5f);
            #pragma unroll
            for (int j = 0; j < 8; j++) {
                float val = (tv[i][j] - mean) * rstd * lgv[j] + lbv[j];
                v[i][j] = fmaxf(val, 0.f);
            }
        }
    }
    storeT(sT1, v);

    zacc(acc);
    __syncthreads();
    loadW(Wg2); __syncthreads();
    gemm(sT1, acc);

    {
        float bias[8];
        #pragma unroll
        for (int j = 0; j < 8; j++) bias[j] = bg2[tx * 8 + j];
        #pragma unroll
        for (int i = 0; i < 4; i++) {
            int row = n0 + ty * 4 + i;
            if (row >= NN) continue;
            float o[8];
            #pragma unroll
            for (int p = 0; p < 4; p++) {
                float2 c = unpk(acc[i][p]);
                o[2 * p + 0] = c.x + bias[2 * p + 0];
                o[2 * p + 1] = c.y + bias[2 * p + 1];
            }
            const float* hrow = sT2 + (ty * 4 + i) * 132 + tx * 8;
            float4 o0 = make_float4(o[0] + hrow[0], o[1] + hrow[1],
                                    o[2] + hrow[2], o[3] + hrow[3]);
            float4 o1 = make_float4(o[4] + hrow[4], o[5] + hrow[5],
                                    o[6] + hrow[6], o[7] + hrow[7]);
            *(float4*)(out + (size_t)row * HH + tx * 8)     = o0;
            *(float4*)(out + (size_t)row * HH + tx * 8 + 4) = o1;
        }
    }
}

// ============================================================================
// Launch
// ============================================================================
extern "C" void kernel_launch(void* const* d_in, const int* in_sizes, int n_in,
                              void* d_out, int out_size)
{
    const float* x        = (const float*)d_in[0];
    const float* feature1 = (const float*)d_in[1];
    const float* feature2 = (const float*)d_in[2];
    const int *pei, *ei;
    const float* ea;
    if (in_sizes[3] == 2 * EE) {
        pei = (const int*)d_in[3]; ei = (const int*)d_in[4];
        ea  = (const float*)d_in[5];
    } else {
        ea  = (const float*)d_in[3];
        pei = (const int*)d_in[4]; ei = (const int*)d_in[5];
    }
    const float* Wf1a   = (const float*)d_in[6];
    const float* bf1a   = (const float*)d_in[7];
    const float* Wf1b   = (const float*)d_in[8];
    const float* bf1b   = (const float*)d_in[9];
    const float* Wf2a   = (const float*)d_in[10];
    const float* bf2a   = (const float*)d_in[11];
    const float* Wf2b   = (const float*)d_in[12];
    const float* bf2b   = (const float*)d_in[13];
    const float* W1_rel = (const float*)d_in[14];
    const float* b1_rel = (const float*)d_in[15];
    const float* W1_root= (const float*)d_in[16];
    const float* W2_rel = (const float*)d_in[17];
    const float* b2_rel = (const float*)d_in[18];
    const float* W2_root= (const float*)d_in[19];
    const float* epsp   = (const float*)d_in[20];
    const float* Wg1    = (const float*)d_in[21];
    const float* bg1    = (const float*)d_in[22];
    const float* lng    = (const float*)d_in[23];
    const float* lnb    = (const float*)d_in[24];
    const float* Wg2    = (const float*)d_in[25];
    const float* bg2    = (const float*)d_in[26];
    const float* Wc     = (const float*)d_in[27];
    const float* bc     = (const float*)d_in[28];
    float* out = (float*)d_out;

    float *agg1, *agg2, *agg3;
    __half *w1a, *w2a, *w1b, *w2b;
    cudaGetSymbolAddress((void**)&agg1, g_agg1);
    cudaGetSymbolAddress((void**)&agg2, g_agg2);
    cudaGetSymbolAddress((void**)&agg3, g_agg3);
    cudaGetSymbolAddress((void**)&w1a, g_W1aT);
    cudaGetSymbolAddress((void**)&w2a, g_W2aT);
    cudaGetSymbolAddress((void**)&w1b, g_W1bT);
    cudaGetSymbolAddress((void**)&w2b, g_W2bT);

    // dynamic smem sizes (see layout math in kernel)
    const int DYN128 = 209408;
    const int DYN32  = 135680;
    cudaFuncSetAttribute(edge_hmma<128>,
                         cudaFuncAttributeMaxDynamicSharedMemorySize, DYN128);
    cudaFuncSetAttribute(edge_hmma<32>,
                         cudaFuncAttributeMaxDynamicSharedMemorySize, DYN32);
    cudaFuncSetAttribute(node_fused,
                         cudaFuncAttributeMaxDynamicSharedMemorySize, 204800);

    prep_weights<<<64, 256>>>(Wf1a, Wf1b, Wf2a, Wf2b);

    cudaMemsetAsync(agg1, 0, sizeof(float) * NN * HH);
    cudaMemsetAsync(agg2, 0, sizeof(float) * NN * HH);
    cudaMemsetAsync(agg3, 0, sizeof(float) * NN * HH);

    edge_hmma<128><<<1172, 256, DYN128>>>(feature1, bf1a, bf1b, x, pei, agg1, w1a, w2a);
    edge_hmma<32><<<1172, 256, DYN32>>>(feature2, bf2a, bf2b, x, pei, agg2, w1b, w2b);
    gine_scatter<<<EE / 8, 256>>>(x, ea, ei, agg3);

    node_fused<<<(NN + 63) / 64, 256, 204800>>>(
        x, W1_rel, b1_rel, W1_root, W2_rel, b2_rel, W2_root,
        Wc, bc, epsp, Wg1, bg1, lng, lnb, Wg2, bg2, out);
}

// round 4
// speedup vs baseline: 4.0917x; 1.4275x over previous
#include <cuda_runtime.h>
#include <cuda_fp16.h>

#define NN 50000
#define EE 600000
#define HH 128
#define MIDD 256

typedef unsigned int u32;
typedef unsigned long long u64;

// ---------------- scratch (device globals) ----------------
__device__ float g_agg1[NN * HH];
__device__ float g_agg2[NN * HH];
__device__ float g_agg3[NN * HH];

// transposed padded fp16 weight images: [n][k] rows, padded strides
__device__ __align__(16) __half g_W1aT[256 * 136];  // Wf1a^T  (k=128, stride 136)
__device__ __align__(16) __half g_W2aT[128 * 264];  // Wf1b^T  (k=256, stride 264)
__device__ __align__(16) __half g_W1bT[256 * 40];   // Wf2a^T  (k=32,  stride 40)
__device__ __align__(16) __half g_W2bT[128 * 264];  // Wf2b^T  (k=256, stride 264)

// node weight images [128n][136k] fp16:
// 0:W1_rel 1:W1_root 2:W2_rel 3:W2_root 4:WcT1 5:WcT2 6:Wg1 7:Wg2
__device__ __align__(16) __half g_nW[8][128 * 136];

// ---------------- helpers ----------------
__device__ __forceinline__ u32 cvta_smem(const void* p) {
    u32 a;
    asm("{ .reg .u64 t; cvta.to.shared.u64 t, %1; cvt.u32.u64 %0, t; }"
        : "=r"(a) : "l"(p));
    return a;
}
__device__ __forceinline__ void ldm4(u32 r[4], u32 addr) {
    asm volatile("ldmatrix.sync.aligned.m8n8.x4.shared.b16 {%0,%1,%2,%3}, [%4];"
        : "=r"(r[0]), "=r"(r[1]), "=r"(r[2]), "=r"(r[3]) : "r"(addr));
}
__device__ __forceinline__ void mma16816(float c[4], const u32 a[4], u32 b0, u32 b1) {
    asm volatile(
        "mma.sync.aligned.m16n8k16.row.col.f32.f16.f16.f32 "
        "{%0,%1,%2,%3}, {%4,%5,%6,%7}, {%8,%9}, {%0,%1,%2,%3};"
        : "+f"(c[0]), "+f"(c[1]), "+f"(c[2]), "+f"(c[3])
        : "r"(a[0]), "r"(a[1]), "r"(a[2]), "r"(a[3]), "r"(b0), "r"(b1));
}
__device__ __forceinline__ u32 pack2(float x, float y) {
    __half2 h = __floats2half2_rn(x, y);
    return *(u32*)&h;
}
__device__ __forceinline__ void red4(float* p, float a, float b, float c, float d) {
    asm volatile("red.global.add.v4.f32 [%0], {%1, %2, %3, %4};"
                 :: "l"(p), "f"(a), "f"(b), "f"(c), "f"(d) : "memory");
}

// ============================================================================
// Weight prep: transpose + fp16 convert into padded [n][k] images.
// ============================================================================
__global__ void prep_weights(const float* __restrict__ Wf1a,
                             const float* __restrict__ Wf1b,
                             const float* __restrict__ Wf2a,
                             const float* __restrict__ Wf2b,
                             const float* __restrict__ W1_rel,
                             const float* __restrict__ W1_root,
                             const float* __restrict__ W2_rel,
                             const float* __restrict__ W2_root,
                             const float* __restrict__ Wc,
                             const float* __restrict__ Wg1,
                             const float* __restrict__ Wg2)
{
    int tid = blockIdx.x * blockDim.x + threadIdx.x;
    int nt = gridDim.x * blockDim.x;
    for (int i = tid; i < 256 * 128; i += nt) {      // W1aT [256n][128k]
        int n = i >> 7, k = i & 127;
        g_W1aT[n * 136 + k] = __float2half(Wf1a[k * 256 + n]);
    }
    for (int i = tid; i < 128 * 256; i += nt) {      // W2aT / W2bT [128n][256k]
        int n = i >> 8, k = i & 255;
        g_W2aT[n * 264 + k] = __float2half(Wf1b[k * 128 + n]);
        g_W2bT[n * 264 + k] = __float2half(Wf2b[k * 128 + n]);
    }
    for (int i = tid; i < 256 * 32; i += nt) {       // W1bT [256n][32k]
        int n = i >> 5, k = i & 31;
        g_W1bT[n * 40 + k] = __float2half(Wf2a[k * 256 + n]);
    }
    for (int i = tid; i < 128 * 128; i += nt) {      // node weights [128n][136k]
        int n = i >> 7, k = i & 127;
        g_nW[0][n * 136 + k] = __float2half(W1_rel[k * 128 + n]);
        g_nW[1][n * 136 + k] = __float2half(W1_root[k * 128 + n]);
        g_nW[2][n * 136 + k] = __float2half(W2_rel[k * 128 + n]);
        g_nW[3][n * 136 + k] = __float2half(W2_root[k * 128 + n]);
        g_nW[4][n * 136 + k] = __float2half(Wc[k * 128 + n]);
        g_nW[5][n * 136 + k] = __float2half(Wc[(k + 128) * 128 + n]);
        g_nW[6][n * 136 + k] = __float2half(Wg1[k * 128 + n]);
        g_nW[7][n * 136 + k] = __float2half(Wg2[k * 128 + n]);
    }
}

// ============================================================================
// Edge MLP via HMMA (unchanged from R3 — validated).
// ============================================================================
template<int DK>
__global__ __launch_bounds__(256, 1) void edge_hmma(
    const float* __restrict__ feat,
    const float* __restrict__ ba, const float* __restrict__ bb,
    const float* __restrict__ x, const int* __restrict__ eidx,
    float* __restrict__ agg,
    const __half* __restrict__ W1T, const __half* __restrict__ W2T)
{
    constexpr int SW1 = DK + 8;
    constexpr int W1SZ = 256 * SW1 * 2;
    constexpr int SW2 = 264;
    constexpr int W2SZ = 128 * SW2 * 2;
    constexpr int SA = DK + 8;
    constexpr int ASZ = 128 * SA * 2;
    constexpr int SF = 136;
    constexpr int OW1 = 0;
    constexpr int OW2 = OW1 + W1SZ;
    constexpr int OA  = OW2 + W2SZ;
    constexpr int OF  = OA + ASZ;
    constexpr int OBA = OF + 128 * SF * 2;
    constexpr int OBB = OBA + 1024;
    constexpr int OSRC = OBB + 512;
    constexpr int ODST = OSRC + 512;
    constexpr int NKT = DK / 16;

    extern __shared__ unsigned char smraw[];
    const u32 sb = cvta_smem(smraw);
    const int tid = threadIdx.x;
    const int w = tid >> 5, lane = tid & 31;
    int* sSrc = (int*)(smraw + OSRC);
    int* sDst = (int*)(smraw + ODST);
    float* sBa = (float*)(smraw + OBA);
    float* sBb = (float*)(smraw + OBB);

    {
        const uint4* w1 = (const uint4*)W1T;
        const uint4* w2 = (const uint4*)W2T;
        uint4* s1 = (uint4*)(smraw + OW1);
        uint4* s2 = (uint4*)(smraw + OW2);
        for (int i = tid; i < W1SZ / 16; i += 256) s1[i] = w1[i];
        for (int i = tid; i < W2SZ / 16; i += 256) s2[i] = w2[i];
        sBa[tid] = ba[tid];
        if (tid < 128) sBb[tid] = bb[tid];
    }

    for (int t = 0; t < 4; t++) {
        const int e0 = (blockIdx.x * 4 + t) * 128;
        __syncthreads();
        if (tid < 128) {
            int e = e0 + tid;
            sSrc[tid] = (e < EE) ? eidx[e] : 0;
            sDst[tid] = (e < EE) ? eidx[EE + e] : 0;
        }
        constexpr int DK4 = DK / 4;
        for (int i = tid; i < 128 * DK4; i += 256) {
            int e = i / DK4, k4 = i % DK4;
            float4 v = make_float4(0.f, 0.f, 0.f, 0.f);
            if (e0 + e < EE) v = *(const float4*)(feat + (size_t)(e0 + e) * DK + k4 * 4);
            __half* dst = (__half*)(smraw + OA) + e * SA + k4 * 4;
            *(u32*)(dst)     = pack2(v.x, v.y);
            *(u32*)(dst + 2) = pack2(v.z, v.w);
        }
        __syncthreads();

        u32 a1[NKT][4];
        #pragma unroll
        for (int kt = 0; kt < NKT; kt++)
            ldm4(a1[kt], sb + OA + ((16 * w + (lane & 15)) * SA + kt * 16 + ((lane >> 4) << 3)) * 2);

        float acc2[16][4];
        #pragma unroll
        for (int j = 0; j < 16; j++)
            #pragma unroll
            for (int q = 0; q < 4; q++) acc2[j][q] = 0.f;

        #pragma unroll
        for (int nc = 0; nc < 4; nc++) {
            float acc1[8][4];
            #pragma unroll
            for (int j = 0; j < 8; j++)
                #pragma unroll
                for (int q = 0; q < 4; q++) acc1[j][q] = 0.f;

            #pragma unroll
            for (int kt = 0; kt < NKT; kt++) {
                #pragma unroll
                for (int nn = 0; nn < 4; nn++) {
                    u32 b[4];
                    ldm4(b, sb + OW1 + ((nc * 64 + nn * 16 + (lane & 7) + ((lane >> 4) << 3)) * SW1
                                        + kt * 16 + (((lane >> 3) & 1) << 3)) * 2);
                    mma16816(acc1[2 * nn],     a1[kt], b[0], b[1]);
                    mma16816(acc1[2 * nn + 1], a1[kt], b[2], b[3]);
                }
            }
            u32 a2[4][4];
            #pragma unroll
            for (int tt = 0; tt < 4; tt++) {
                int c0 = nc * 64 + tt * 16 + 2 * (lane & 3);
                float b0 = sBa[c0], b1 = sBa[c0 + 1];
                float b8 = sBa[c0 + 8], b9 = sBa[c0 + 9];
                a2[tt][0] = pack2(fmaxf(acc1[2 * tt][0] + b0, 0.f),
                                  fmaxf(acc1[2 * tt][1] + b1, 0.f));
                a2[tt][1] = pack2(fmaxf(acc1[2 * tt][2] + b0, 0.f),
                                  fmaxf(acc1[2 * tt][3] + b1, 0.f));
                a2[tt][2] = pack2(fmaxf(acc1[2 * tt + 1][0] + b8, 0.f),
                                  fmaxf(acc1[2 * tt + 1][1] + b9, 0.f));
                a2[tt][3] = pack2(fmaxf(acc1[2 * tt + 1][2] + b8, 0.f),
                                  fmaxf(acc1[2 * tt + 1][3] + b9, 0.f));
            }
            #pragma unroll
            for (int tt = 0; tt < 4; tt++) {
                #pragma unroll
                for (int nn = 0; nn < 8; nn++) {
                    u32 b[4];
                    ldm4(b, sb + OW2 + ((nn * 16 + (lane & 7) + ((lane >> 4) << 3)) * SW2
                                        + nc * 64 + tt * 16 + (((lane >> 3) & 1) << 3)) * 2);
                    mma16816(acc2[2 * nn],     a2[tt], b[0], b[1]);
                    mma16816(acc2[2 * nn + 1], a2[tt], b[2], b[3]);
                }
            }
        }

        {
            __half* F = (__half*)(smraw + OF);
            int row = 16 * w + (lane >> 2);
            #pragma unroll
            for (int j = 0; j < 16; j++) {
                int col = j * 8 + 2 * (lane & 3);
                *(u32*)(F + row * SF + col)       = pack2(acc2[j][0], acc2[j][1]);
                *(u32*)(F + (row + 8) * SF + col) = pack2(acc2[j][2], acc2[j][3]);
            }
        }
        __syncthreads();

        {
            int e = tid >> 1;
            int ch = (tid & 1) * 64;
            if (e0 + e < EE) {
                int src = sSrc[e], dst = sDst[e];
                const __half* Fr = (const __half*)(smraw + OF) + e * SF + ch;
                const float4* xr = (const float4*)(x + (size_t)src * HH + ch);
                const float4* bbp = (const float4*)(sBb + ch);
                float* ap = agg + (size_t)dst * HH + ch;
                #pragma unroll
                for (int q = 0; q < 16; q++) {
                    float4 xv = __ldg(xr + q);
                    float4 bv = bbp[q];
                    float2 f0 = __half22float2(*(const __half2*)(Fr + q * 4));
                    float2 f1 = __half22float2(*(const __half2*)(Fr + q * 4 + 2));
                    red4(ap + q * 4,
                         (f0.x + bv.x) * xv.x, (f0.y + bv.y) * xv.y,
                         (f1.x + bv.z) * xv.z, (f1.y + bv.w) * xv.w);
                }
            }
        }
    }
}

// ============================================================================
// GINE scatter (unchanged).
// ============================================================================
__global__ __launch_bounds__(256) void gine_scatter(
    const float* __restrict__ x, const float* __restrict__ ea,
    const int* __restrict__ eidx, float* __restrict__ agg3)
{
    int e = blockIdx.x * 8 + (threadIdx.x >> 5);
    int lane = threadIdx.x & 31;
    int s = eidx[e];
    int d = eidx[EE + e];
    float4 v  = *(const float4*)(ea + (size_t)e * HH + lane * 4);
    float4 xv = *(const float4*)(x  + (size_t)s * HH + lane * 4);
    red4(agg3 + (size_t)d * HH + lane * 4, v.x + xv.x, v.y + xv.y, v.z + xv.z, v.w + xv.w);
}

// ============================================================================
// Node-level fused via HMMA: 128 nodes/CTA, 8 warps, all GEMMs m16n8k16 fp16.
// smem: OA [128][136] fp16 stage (34816B), OW weight [128][136] (34816B),
//       biases 7*512B at OBIAS. Total 73216B.
// ============================================================================
#define NOA 0
#define NOW 34816
#define NOB 69632
#define NODE_DYN 73216

__global__ __launch_bounds__(256, 1) void node_hmma(
    const float* __restrict__ x,
    const float* __restrict__ b1_rel, const float* __restrict__ b2_rel,
    const float* __restrict__ bc, const float* __restrict__ epsp,
    const float* __restrict__ bg1,
    const float* __restrict__ lng, const float* __restrict__ lnb,
    const float* __restrict__ bg2,
    float* __restrict__ out)
{
    extern __shared__ unsigned char smraw[];
    const u32 sb = cvta_smem(smraw);
    const int tid = threadIdx.x;
    const int w = tid >> 5, lane = tid & 31;
    const int n0 = blockIdx.x * 128;

    float* sB1 = (float*)(smraw + NOB);
    float* sB2 = sB1 + 128;
    float* sBc = sB2 + 128;
    float* sBg1 = sBc + 128;
    float* sLg = sBg1 + 128;
    float* sLb = sLg + 128;
    float* sBg2 = sLb + 128;

    auto stageA = [&](const float* src) {
        for (int i = tid; i < 128 * 32; i += 256) {
            int n = i >> 5, k4 = i & 31;
            int row = n0 + n;
            float4 v = make_float4(0.f, 0.f, 0.f, 0.f);
            if (row < NN) v = *(const float4*)(src + (size_t)row * HH + k4 * 4);
            __half* dst = (__half*)(smraw + NOA) + n * 136 + k4 * 4;
            *(u32*)(dst)     = pack2(v.x, v.y);
            *(u32*)(dst + 2) = pack2(v.z, v.w);
        }
    };
    auto loadW = [&](int wi) {
        const uint4* src = (const uint4*)g_nW[wi];
        uint4* dst = (uint4*)(smraw + NOW);
        for (int i = tid; i < 2176; i += 256) dst[i] = src[i];
    };
    auto ldA = [&](u32 fr[8][4]) {
        #pragma unroll
        for (int kt = 0; kt < 8; kt++)
            ldm4(fr[kt], sb + NOA + ((16 * w + (lane & 15)) * 136 + kt * 16 + ((lane >> 4) << 3)) * 2);
    };
    auto gemmB = [&](const u32 fr[8][4], float acc[16][4]) {
        #pragma unroll
        for (int kt = 0; kt < 8; kt++) {
            #pragma unroll
            for (int nn = 0; nn < 8; nn++) {
                u32 b[4];
                ldm4(b, sb + NOW + ((nn * 16 + (lane & 7) + ((lane >> 4) << 3)) * 136
                                    + kt * 16 + (((lane >> 3) & 1) << 3)) * 2);
                mma16816(acc[2 * nn],     fr[kt], b[0], b[1]);
                mma16816(acc[2 * nn + 1], fr[kt], b[2], b[3]);
            }
        }
    };
    auto zacc = [&](float acc[16][4]) {
        #pragma unroll
        for (int j = 0; j < 16; j++)
            #pragma unroll
            for (int q = 0; q < 4; q++) acc[j][q] = 0.f;
    };
    auto repack_relu = [&](const float acc[16][4], const float* bias, u32 fr[8][4]) {
        #pragma unroll
        for (int tt = 0; tt < 8; tt++) {
            int c0 = tt * 16 + 2 * (lane & 3);
            float b0 = bias[c0], b1 = bias[c0 + 1];
            float b8 = bias[c0 + 8], b9 = bias[c0 + 9];
            fr[tt][0] = pack2(fmaxf(acc[2 * tt][0] + b0, 0.f),
                              fmaxf(acc[2 * tt][1] + b1, 0.f));
            fr[tt][1] = pack2(fmaxf(acc[2 * tt][2] + b0, 0.f),
                              fmaxf(acc[2 * tt][3] + b1, 0.f));
            fr[tt][2] = pack2(fmaxf(acc[2 * tt + 1][0] + b8, 0.f),
                              fmaxf(acc[2 * tt + 1][1] + b9, 0.f));
            fr[tt][3] = pack2(fmaxf(acc[2 * tt + 1][2] + b8, 0.f),
                              fmaxf(acc[2 * tt + 1][3] + b9, 0.f));
        }
    };

    // ---------- stage x, biases, W1_rel ----------
    stageA(x);
    loadW(0);
    if (tid < 128) {
        sB1[tid] = b1_rel[tid]; sB2[tid] = b2_rel[tid]; sBc[tid] = bc[tid];
        sBg1[tid] = bg1[tid]; sLg[tid] = lng[tid]; sLb[tid] = lnb[tid];
        sBg2[tid] = bg2[tid];
    }
    __syncthreads();

    u32 xf[8][4];
    ldA(xf);
    __syncthreads();

    float acc[16][4];

    // ---------- h1 ----------
    stageA(g_agg1);
    __syncthreads();
    u32 af[8][4];
    ldA(af);
    zacc(acc);
    gemmB(af, acc);            // agg1 @ W1_rel
    __syncthreads();
    loadW(1);
    __syncthreads();
    gemmB(xf, acc);            // + x @ W1_root
    u32 h1f[8][4];
    repack_relu(acc, sB1, h1f);
    __syncthreads();

    // ---------- h2 ----------
    stageA(g_agg2);
    loadW(2);
    __syncthreads();
    ldA(af);
    zacc(acc);
    gemmB(af, acc);            // agg2 @ W2_rel
    __syncthreads();
    loadW(3);
    __syncthreads();
    gemmB(xf, acc);            // + x @ W2_root
    u32 h2f[8][4];
    repack_relu(acc, sB2, h2f);
    __syncthreads();

    // ---------- h = relu(cat @ Wc + bc) ----------
    loadW(4);
    __syncthreads();
    zacc(acc);
    gemmB(h1f, acc);
    __syncthreads();
    loadW(5);
    __syncthreads();
    gemmB(h2f, acc);
    float hC[16][4];
    #pragma unroll
    for (int j = 0; j < 16; j++) {
        int c = j * 8 + 2 * (lane & 3);
        hC[j][0] = fmaxf(acc[j][0] + sBc[c],     0.f);
        hC[j][1] = fmaxf(acc[j][1] + sBc[c + 1], 0.f);
        hC[j][2] = fmaxf(acc[j][2] + sBc[c],     0.f);
        hC[j][3] = fmaxf(acc[j][3] + sBc[c + 1], 0.f);
    }
    __syncthreads();

    // ---------- g = (1+eps)*x + agg3 -> fp16 stage ----------
    {
        float epsv = 1.0f + *epsp;
        for (int i = tid; i < 128 * 32; i += 256) {
            int n = i >> 5, k4 = i & 31;
            int row = n0 + n;
            float4 xv = make_float4(0.f, 0.f, 0.f, 0.f);
            float4 av = make_float4(0.f, 0.f, 0.f, 0.f);
            if (row < NN) {
                xv = *(const float4*)(x + (size_t)row * HH + k4 * 4);
                av = *(const float4*)(g_agg3 + (size_t)row * HH + k4 * 4);
            }
            __half* dst = (__half*)(smraw + NOA) + n * 136 + k4 * 4;
            *(u32*)(dst)     = pack2(xv.x * epsv + av.x, xv.y * epsv + av.y);
            *(u32*)(dst + 2) = pack2(xv.z * epsv + av.z, xv.w * epsv + av.w);
        }
    }
    loadW(6);
    __syncthreads();

    // ---------- t = g @ Wg1 + bg1; LN; relu; repack ----------
    ldA(af);                     // g fragments
    zacc(acc);
    gemmB(af, acc);

    u32 tf[8][4];
    {
        float sA = 0.f, qA = 0.f, sBv = 0.f, qB = 0.f;
        #pragma unroll
        for (int j = 0; j < 16; j++) {
            int c = j * 8 + 2 * (lane & 3);
            acc[j][0] += sBg1[c];
            acc[j][1] += sBg1[c + 1];
            acc[j][2] += sBg1[c];
            acc[j][3] += sBg1[c + 1];
            sA += acc[j][0] + acc[j][1];
            qA += acc[j][0] * acc[j][0] + acc[j][1] * acc[j][1];
            sBv += acc[j][2] + acc[j][3];
            qB += acc[j][2] * acc[j][2] + acc[j][3] * acc[j][3];
        }
        #pragma unroll
        for (int d = 1; d < 4; d <<= 1) {
            sA  += __shfl_xor_sync(0xffffffffu, sA, d);
            qA  += __shfl_xor_sync(0xffffffffu, qA, d);
            sBv += __shfl_xor_sync(0xffffffffu, sBv, d);
            qB  += __shfl_xor_sync(0xffffffffu, qB, d);
        }
        float mA = sA * (1.f / 128.f);
        float vA = qA * (1.f / 128.f) - mA * mA;
        float rA = rsqrtf(vA + 1e-5f);
        float mB = sBv * (1.f / 128.f);
        float vB = qB * (1.f / 128.f) - mB * mB;
        float rB = rsqrtf(vB + 1e-5f);
        #pragma unroll
        for (int j = 0; j < 16; j++) {
            int c = j * 8 + 2 * (lane & 3);
            float g0 = sLg[c], g1 = sLg[c + 1], l0 = sLb[c], l1 = sLb[c + 1];
            acc[j][0] = fmaxf((acc[j][0] - mA) * rA * g0 + l0, 0.f);
            acc[j][1] = fmaxf((acc[j][1] - mA) * rA * g1 + l1, 0.f);
            acc[j][2] = fmaxf((acc[j][2] - mB) * rB * g0 + l0, 0.f);
            acc[j][3] = fmaxf((acc[j][3] - mB) * rB * g1 + l1, 0.f);
        }
        #pragma unroll
        for (int tt = 0; tt < 8; tt++) {
            tf[tt][0] = pack2(acc[2 * tt][0],     acc[2 * tt][1]);
            tf[tt][1] = pack2(acc[2 * tt][2],     acc[2 * tt][3]);
            tf[tt][2] = pack2(acc[2 * tt + 1][0], acc[2 * tt + 1][1]);
            tf[tt][3] = pack2(acc[2 * tt + 1][2], acc[2 * tt + 1][3]);
        }
    }
    __syncthreads();
    loadW(7);
    __syncthreads();

    // ---------- h3 = t @ Wg2 + bg2 ; out = h + h3 ----------
    zacc(acc);
    gemmB(tf, acc);
    {
        int r0 = n0 + 16 * w + (lane >> 2);
        int r1 = r0 + 8;
        #pragma unroll
        for (int j = 0; j < 16; j++) {
            int c = j * 8 + 2 * (lane & 3);
            float b0 = sBg2[c], b1 = sBg2[c + 1];
            if (r0 < NN) {
                float2 o = make_float2(hC[j][0] + acc[j][0] + b0,
                                       hC[j][1] + acc[j][1] + b1);
                *(float2*)(out + (size_t)r0 * HH + c) = o;
            }
            if (r1 < NN) {
                float2 o = make_float2(hC[j][2] + acc[j][2] + b0,
                                       hC[j][3] + acc[j][3] + b1);
                *(float2*)(out + (size_t)r1 * HH + c) = o;
            }
        }
    }
}

// ============================================================================
// Launch
// ============================================================================
extern "C" void kernel_launch(void* const* d_in, const int* in_sizes, int n_in,
                              void* d_out, int out_size)
{
    const float* x        = (const float*)d_in[0];
    const float* feature1 = (const float*)d_in[1];
    const float* feature2 = (const float*)d_in[2];
    const int *pei, *ei;
    const float* ea;
    if (in_sizes[3] == 2 * EE) {
        pei = (const int*)d_in[3]; ei = (const int*)d_in[4];
        ea  = (const float*)d_in[5];
    } else {
        ea  = (const float*)d_in[3];
        pei = (const int*)d_in[4]; ei = (const int*)d_in[5];
    }
    const float* Wf1a   = (const float*)d_in[6];
    const float* bf1a   = (const float*)d_in[7];
    const float* Wf1b   = (const float*)d_in[8];
    const float* bf1b   = (const float*)d_in[9];
    const float* Wf2a   = (const float*)d_in[10];
    const float* bf2a   = (const float*)d_in[11];
    const float* Wf2b   = (const float*)d_in[12];
    const float* bf2b   = (const float*)d_in[13];
    const float* W1_rel = (const float*)d_in[14];
    const float* b1_rel = (const float*)d_in[15];
    const float* W1_root= (const float*)d_in[16];
    const float* W2_rel = (const float*)d_in[17];
    const float* b2_rel = (const float*)d_in[18];
    const float* W2_root= (const float*)d_in[19];
    const float* epsp   = (const float*)d_in[20];
    const float* Wg1    = (const float*)d_in[21];
    const float* bg1    = (const float*)d_in[22];
    const float* lng    = (const float*)d_in[23];
    const float* lnb    = (const float*)d_in[24];
    const float* Wg2    = (const float*)d_in[25];
    const float* bg2    = (const float*)d_in[26];
    const float* Wc     = (const float*)d_in[27];
    const float* bc     = (const float*)d_in[28];
    float* out = (float*)d_out;

    float *agg1, *agg2, *agg3;
    __half *w1a, *w2a, *w1b, *w2b;
    cudaGetSymbolAddress((void**)&agg1, g_agg1);
    cudaGetSymbolAddress((void**)&agg2, g_agg2);
    cudaGetSymbolAddress((void**)&agg3, g_agg3);
    cudaGetSymbolAddress((void**)&w1a, g_W1aT);
    cudaGetSymbolAddress((void**)&w2a, g_W2aT);
    cudaGetSymbolAddress((void**)&w1b, g_W1bT);
    cudaGetSymbolAddress((void**)&w2b, g_W2bT);

    const int DYN128 = 209408;
    const int DYN32  = 135680;
    cudaFuncSetAttribute(edge_hmma<128>,
                         cudaFuncAttributeMaxDynamicSharedMemorySize, DYN128);
    cudaFuncSetAttribute(edge_hmma<32>,
                         cudaFuncAttributeMaxDynamicSharedMemorySize, DYN32);
    cudaFuncSetAttribute(node_hmma,
                         cudaFuncAttributeMaxDynamicSharedMemorySize, NODE_DYN);

    prep_weights<<<64, 256>>>(Wf1a, Wf1b, Wf2a, Wf2b,
                              W1_rel, W1_root, W2_rel, W2_root, Wc, Wg1, Wg2);

    cudaMemsetAsync(agg1, 0, sizeof(float) * NN * HH);
    cudaMemsetAsync(agg2, 0, sizeof(float) * NN * HH);
    cudaMemsetAsync(agg3, 0, sizeof(float) * NN * HH);

    edge_hmma<128><<<1172, 256, DYN128>>>(feature1, bf1a, bf1b, x, pei, agg1, w1a, w2a);
    edge_hmma<32><<<1172, 256, DYN32>>>(feature2, bf2a, bf2b, x, pei, agg2, w1b, w2b);
    gine_scatter<<<EE / 8, 256>>>(x, ea, ei, agg3);

    node_hmma<<<(NN + 127) / 128, 256, NODE_DYN>>>(
        x, b1_rel, b2_rel, bc, epsp, bg1, lng, lnb, bg2, out);
}

// round 5
// speedup vs baseline: 4.5584x; 1.1141x over previous
#include <cuda_runtime.h>
#include <cuda_fp16.h>

#define NN 50000
#define EE 600000
#define HH 128
#define MIDD 256

typedef unsigned int u32;
typedef unsigned long long u64;

// ---------------- scratch (device globals) ----------------
__device__ float g_agg1[NN * HH];
__device__ float g_agg2[NN * HH];
__device__ float g_agg3[NN * HH];

// transposed padded fp16 weight images: [n][k] rows, padded strides
__device__ __align__(16) __half g_W1aT[256 * 136];  // Wf1a^T  (k=128, stride 136)
__device__ __align__(16) __half g_W2aT[128 * 264];  // Wf1b^T  (k=256, stride 264)
__device__ __align__(16) __half g_W1bT[256 * 40];   // Wf2a^T  (k=32,  stride 40)
__device__ __align__(16) __half g_W2bT[128 * 264];  // Wf2b^T  (k=256, stride 264)

// node weight images [128n][136k] fp16:
// 0:W1_rel 1:W1_root 2:W2_rel 3:W2_root 4:WcT1 5:WcT2 6:Wg1 7:Wg2
__device__ __align__(16) __half g_nW[8][128 * 136];

// ---------------- helpers ----------------
__device__ __forceinline__ u32 cvta_smem(const void* p) {
    u32 a;
    asm("{ .reg .u64 t; cvta.to.shared.u64 t, %1; cvt.u32.u64 %0, t; }"
        : "=r"(a) : "l"(p));
    return a;
}
__device__ __forceinline__ void ldm4(u32 r[4], u32 addr) {
    asm volatile("ldmatrix.sync.aligned.m8n8.x4.shared.b16 {%0,%1,%2,%3}, [%4];"
        : "=r"(r[0]), "=r"(r[1]), "=r"(r[2]), "=r"(r[3]) : "r"(addr));
}
__device__ __forceinline__ void mma16816(float c[4], const u32 a[4], u32 b0, u32 b1) {
    asm volatile(
        "mma.sync.aligned.m16n8k16.row.col.f32.f16.f16.f32 "
        "{%0,%1,%2,%3}, {%4,%5,%6,%7}, {%8,%9}, {%0,%1,%2,%3};"
        : "+f"(c[0]), "+f"(c[1]), "+f"(c[2]), "+f"(c[3])
        : "r"(a[0]), "r"(a[1]), "r"(a[2]), "r"(a[3]), "r"(b0), "r"(b1));
}
__device__ __forceinline__ u32 pack2(float x, float y) {
    __half2 h = __floats2half2_rn(x, y);
    return *(u32*)&h;
}
__device__ __forceinline__ void red4(float* p, float a, float b, float c, float d) {
    asm volatile("red.global.add.v4.f32 [%0], {%1, %2, %3, %4};"
                 :: "l"(p), "f"(a), "f"(b), "f"(c), "f"(d) : "memory");
}

// ============================================================================
// Weight prep: transpose + fp16 convert into padded [n][k] images.
// ============================================================================
__global__ void prep_weights(const float* __restrict__ Wf1a,
                             const float* __restrict__ Wf1b,
                             const float* __restrict__ Wf2a,
                             const float* __restrict__ Wf2b,
                             const float* __restrict__ W1_rel,
                             const float* __restrict__ W1_root,
                             const float* __restrict__ W2_rel,
                             const float* __restrict__ W2_root,
                             const float* __restrict__ Wc,
                             const float* __restrict__ Wg1,
                             const float* __restrict__ Wg2)
{
    int tid = blockIdx.x * blockDim.x + threadIdx.x;
    int nt = gridDim.x * blockDim.x;
    for (int i = tid; i < 256 * 128; i += nt) {      // W1aT [256n][128k]
        int n = i >> 7, k = i & 127;
        g_W1aT[n * 136 + k] = __float2half(Wf1a[k * 256 + n]);
    }
    for (int i = tid; i < 128 * 256; i += nt) {      // W2aT / W2bT [128n][256k]
        int n = i >> 8, k = i & 255;
        g_W2aT[n * 264 + k] = __float2half(Wf1b[k * 128 + n]);
        g_W2bT[n * 264 + k] = __float2half(Wf2b[k * 128 + n]);
    }
    for (int i = tid; i < 256 * 32; i += nt) {       // W1bT [256n][32k]
        int n = i >> 5, k = i & 31;
        g_W1bT[n * 40 + k] = __float2half(Wf2a[k * 256 + n]);
    }
    for (int i = tid; i < 128 * 128; i += nt) {      // node weights [128n][136k]
        int n = i >> 7, k = i & 127;
        g_nW[0][n * 136 + k] = __float2half(W1_rel[k * 128 + n]);
        g_nW[1][n * 136 + k] = __float2half(W1_root[k * 128 + n]);
        g_nW[2][n * 136 + k] = __float2half(W2_rel[k * 128 + n]);
        g_nW[3][n * 136 + k] = __float2half(W2_root[k * 128 + n]);
        g_nW[4][n * 136 + k] = __float2half(Wc[k * 128 + n]);
        g_nW[5][n * 136 + k] = __float2half(Wc[(k + 128) * 128 + n]);
        g_nW[6][n * 136 + k] = __float2half(Wg1[k * 128 + n]);
        g_nW[7][n * 136 + k] = __float2half(Wg2[k * 128 + n]);
    }
}

// ============================================================================
// Edge MLP via HMMA with cross-tile register prefetch (8 tiles/CTA):
//   mid = relu(feat @ Wa + ba); f = mid @ Wb; agg[dst] += (f+bb)*x[src]
// A double-buffered; F aliases the consumed A buffer when DK==128.
// ============================================================================
#define ETILES 8

template<int DK>
__global__ __launch_bounds__(256, 1) void edge_hmma(
    const float* __restrict__ feat,
    const float* __restrict__ ba, const float* __restrict__ bb,
    const float* __restrict__ x, const int* __restrict__ eidx,
    float* __restrict__ agg,
    const __half* __restrict__ W1T, const __half* __restrict__ W2T)
{
    constexpr int SW1 = DK + 8;
    constexpr int W1SZ = 256 * SW1 * 2;
    constexpr int SW2 = 264;
    constexpr int W2SZ = 128 * SW2 * 2;
    constexpr int SA = DK + 8;
    constexpr int ASZ = 128 * SA * 2;
    constexpr int SF = 136;
    constexpr int OW1 = 0;
    constexpr int OW2 = OW1 + W1SZ;
    constexpr int OA0 = OW2 + W2SZ;
    constexpr int OA1 = OA0 + ASZ;
    constexpr int OFS = OA1 + ASZ;                    // separate F (DK!=128 only)
    constexpr int FSZ = (DK == 128) ? 0 : 128 * SF * 2;
    constexpr int OBA = OFS + FSZ;
    constexpr int OBB = OBA + 1024;
    constexpr int OIDX = OBB + 512;                   // int sIdx[2][256]
    constexpr int NKT = DK / 16;
    constexpr int DK4 = DK / 4;
    constexpr int LD = DK / 8;                        // float4 loads / thread / tile

    extern __shared__ unsigned char smraw[];
    const u32 sb = cvta_smem(smraw);
    const int tid = threadIdx.x;
    const int w = tid >> 5, lane = tid & 31;
    float* sBa = (float*)(smraw + OBA);
    float* sBb = (float*)(smraw + OBB);
    int* sIdx = (int*)(smraw + OIDX);

    // stage weights + biases
    {
        const uint4* w1 = (const uint4*)W1T;
        const uint4* w2 = (const uint4*)W2T;
        uint4* s1 = (uint4*)(smraw + OW1);
        uint4* s2 = (uint4*)(smraw + OW2);
        for (int i = tid; i < W1SZ / 16; i += 256) s1[i] = w1[i];
        for (int i = tid; i < W2SZ / 16; i += 256) s2[i] = w2[i];
        sBa[tid] = ba[tid];
        if (tid < 128) sBb[tid] = bb[tid];
    }

    u32 pf[2 * LD];
    int pfS = 0, pfD = 0;

    auto load_pf = [&](int t) {
        const int e0 = (blockIdx.x * ETILES + t) * 128;
        #pragma unroll
        for (int j = 0; j < LD; j++) {
            int i = tid + j * 256;
            int e = i / DK4, k4 = i % DK4;
            float4 v = make_float4(0.f, 0.f, 0.f, 0.f);
            if (e0 + e < EE) v = *(const float4*)(feat + (size_t)(e0 + e) * DK + k4 * 4);
            pf[2 * j]     = pack2(v.x, v.y);
            pf[2 * j + 1] = pack2(v.z, v.w);
        }
        if (tid < 128) {
            int e = e0 + tid;
            pfS = (e < EE) ? eidx[e] : 0;
            pfD = (e < EE) ? eidx[EE + e] : 0;
        }
    };
    auto store_pf = [&](int buf) {
        __half* base = (__half*)(smraw + (buf ? OA1 : OA0));
        #pragma unroll
        for (int j = 0; j < LD; j++) {
            int i = tid + j * 256;
            int e = i / DK4, k4 = i % DK4;
            *(uint2*)(base + e * SA + k4 * 4) = make_uint2(pf[2 * j], pf[2 * j + 1]);
        }
        if (tid < 128) {
            sIdx[buf * 256 + tid] = pfS;
            sIdx[buf * 256 + 128 + tid] = pfD;
        }
    };

    load_pf(0);

    for (int t = 0; t < ETILES; t++) {
        const int buf = t & 1;
        const int e0 = (blockIdx.x * ETILES + t) * 128;
        store_pf(buf);
        __syncthreads();                       // A/idx ready; prior scatter done

        const u32 abase = sb + (buf ? OA1 : OA0);
        u32 a1[NKT][4];
        #pragma unroll
        for (int kt = 0; kt < NKT; kt++)
            ldm4(a1[kt], abase + ((16 * w + (lane & 15)) * SA + kt * 16 + ((lane >> 4) << 3)) * 2);

        if (t + 1 < ETILES) load_pf(t + 1);    // overlap next tile's DRAM with MMA

        float acc2[16][4];
        #pragma unroll
        for (int j = 0; j < 16; j++)
            #pragma unroll
            for (int q = 0; q < 4; q++) acc2[j][q] = 0.f;

        #pragma unroll
        for (int nc = 0; nc < 4; nc++) {
            float acc1[8][4];
            #pragma unroll
            for (int j = 0; j < 8; j++)
                #pragma unroll
                for (int q = 0; q < 4; q++) acc1[j][q] = 0.f;

            #pragma unroll
            for (int kt = 0; kt < NKT; kt++) {
                #pragma unroll
                for (int nn = 0; nn < 4; nn++) {
                    u32 b[4];
                    ldm4(b, sb + OW1 + ((nc * 64 + nn * 16 + (lane & 7) + ((lane >> 4) << 3)) * SW1
                                        + kt * 16 + (((lane >> 3) & 1) << 3)) * 2);
                    mma16816(acc1[2 * nn],     a1[kt], b[0], b[1]);
                    mma16816(acc1[2 * nn + 1], a1[kt], b[2], b[3]);
                }
            }
            u32 a2[4][4];
            #pragma unroll
            for (int tt = 0; tt < 4; tt++) {
                int c0 = nc * 64 + tt * 16 + 2 * (lane & 3);
                float b0 = sBa[c0], b1 = sBa[c0 + 1];
                float b8 = sBa[c0 + 8], b9 = sBa[c0 + 9];
                a2[tt][0] = pack2(fmaxf(acc1[2 * tt][0] + b0, 0.f),
                                  fmaxf(acc1[2 * tt][1] + b1, 0.f));
                a2[tt][1] = pack2(fmaxf(acc1[2 * tt][2] + b0, 0.f),
                                  fmaxf(acc1[2 * tt][3] + b1, 0.f));
                a2[tt][2] = pack2(fmaxf(acc1[2 * tt + 1][0] + b8, 0.f),
                                  fmaxf(acc1[2 * tt + 1][1] + b9, 0.f));
                a2[tt][3] = pack2(fmaxf(acc1[2 * tt + 1][2] + b8, 0.f),
                                  fmaxf(acc1[2 * tt + 1][3] + b9, 0.f));
            }
            #pragma unroll
            for (int tt = 0; tt < 4; tt++) {
                #pragma unroll
                for (int nn = 0; nn < 8; nn++) {
                    u32 b[4];
                    ldm4(b, sb + OW2 + ((nn * 16 + (lane & 7) + ((lane >> 4) << 3)) * SW2
                                        + nc * 64 + tt * 16 + (((lane >> 3) & 1) << 3)) * 2);
                    mma16816(acc2[2 * nn],     a2[tt], b[0], b[1]);
                    mma16816(acc2[2 * nn + 1], a2[tt], b[2], b[3]);
                }
            }
        }

        // store f to smem fp16 (aliases A[buf] when DK==128; same warp-row range
        // as the a1 ldmatrix reads, so no extra barrier is needed)
        __half* F = (DK == 128) ? (__half*)(smraw + (buf ? OA1 : OA0))
                                : (__half*)(smraw + OFS);
        {
            int row = 16 * w + (lane >> 2);
            #pragma unroll
            for (int j = 0; j < 16; j++) {
                int col = j * 8 + 2 * (lane & 3);
                *(u32*)(F + row * SF + col)       = pack2(acc2[j][0], acc2[j][1]);
                *(u32*)(F + (row + 8) * SF + col) = pack2(acc2[j][2], acc2[j][3]);
            }
        }
        __syncthreads();                       // F + idx visible to scatter

        {
            int e = tid >> 1;
            int ch = (tid & 1) * 64;
            if (e0 + e < EE) {
                int src = sIdx[buf * 256 + e];
                int dst = sIdx[buf * 256 + 128 + e];
                const __half* Fr = F + e * SF + ch;
                const float4* xr = (const float4*)(x + (size_t)src * HH + ch);
                const float4* bbp = (const float4*)(sBb + ch);
                float* ap = agg + (size_t)dst * HH + ch;
                #pragma unroll
                for (int q = 0; q < 16; q++) {
                    float4 xv = __ldg(xr + q);
                    float4 bv = bbp[q];
                    float2 f0 = __half22float2(*(const __half2*)(Fr + q * 4));
                    float2 f1 = __half22float2(*(const __half2*)(Fr + q * 4 + 2));
                    red4(ap + q * 4,
                         (f0.x + bv.x) * xv.x, (f0.y + bv.y) * xv.y,
                         (f1.x + bv.z) * xv.z, (f1.y + bv.w) * xv.w);
                }
            }
        }
    }
}

// ============================================================================
// GINE scatter (unchanged).
// ============================================================================
__global__ __launch_bounds__(256) void gine_scatter(
    const float* __restrict__ x, const float* __restrict__ ea,
    const int* __restrict__ eidx, float* __restrict__ agg3)
{
    int e = blockIdx.x * 8 + (threadIdx.x >> 5);
    int lane = threadIdx.x & 31;
    int s = eidx[e];
    int d = eidx[EE + e];
    float4 v  = *(const float4*)(ea + (size_t)e * HH + lane * 4);
    float4 xv = *(const float4*)(x  + (size_t)s * HH + lane * 4);
    red4(agg3 + (size_t)d * HH + lane * 4, v.x + xv.x, v.y + xv.y, v.z + xv.z, v.w + xv.w);
}

// ============================================================================
// Node-level fused via HMMA (unchanged from R4 — validated).
// ============================================================================
#define NOA 0
#define NOW 34816
#define NOB 69632
#define NODE_DYN 73216

__global__ __launch_bounds__(256, 1) void node_hmma(
    const float* __restrict__ x,
    const float* __restrict__ b1_rel, const float* __restrict__ b2_rel,
    const float* __restrict__ bc, const float* __restrict__ epsp,
    const float* __restrict__ bg1,
    const float* __restrict__ lng, const float* __restrict__ lnb,
    const float* __restrict__ bg2,
    float* __restrict__ out)
{
    extern __shared__ unsigned char smraw[];
    const u32 sb = cvta_smem(smraw);
    const int tid = threadIdx.x;
    const int w = tid >> 5, lane = tid & 31;
    const int n0 = blockIdx.x * 128;

    float* sB1 = (float*)(smraw + NOB);
    float* sB2 = sB1 + 128;
    float* sBc = sB2 + 128;
    float* sBg1 = sBc + 128;
    float* sLg = sBg1 + 128;
    float* sLb = sLg + 128;
    float* sBg2 = sLb + 128;

    auto stageA = [&](const float* src) {
        for (int i = tid; i < 128 * 32; i += 256) {
            int n = i >> 5, k4 = i & 31;
            int row = n0 + n;
            float4 v = make_float4(0.f, 0.f, 0.f, 0.f);
            if (row < NN) v = *(const float4*)(src + (size_t)row * HH + k4 * 4);
            __half* dst = (__half*)(smraw + NOA) + n * 136 + k4 * 4;
            *(u32*)(dst)     = pack2(v.x, v.y);
            *(u32*)(dst + 2) = pack2(v.z, v.w);
        }
    };
    auto loadW = [&](int wi) {
        const uint4* src = (const uint4*)g_nW[wi];
        uint4* dst = (uint4*)(smraw + NOW);
        for (int i = tid; i < 2176; i += 256) dst[i] = src[i];
    };
    auto ldA = [&](u32 fr[8][4]) {
        #pragma unroll
        for (int kt = 0; kt < 8; kt++)
            ldm4(fr[kt], sb + NOA + ((16 * w + (lane & 15)) * 136 + kt * 16 + ((lane >> 4) << 3)) * 2);
    };
    auto gemmB = [&](const u32 fr[8][4], float acc[16][4]) {
        #pragma unroll
        for (int kt = 0; kt < 8; kt++) {
            #pragma unroll
            for (int nn = 0; nn < 8; nn++) {
                u32 b[4];
                ldm4(b, sb + NOW + ((nn * 16 + (lane & 7) + ((lane >> 4) << 3)) * 136
                                    + kt * 16 + (((lane >> 3) & 1) << 3)) * 2);
                mma16816(acc[2 * nn],     fr[kt], b[0], b[1]);
                mma16816(acc[2 * nn + 1], fr[kt], b[2], b[3]);
            }
        }
    };
    auto zacc = [&](float acc[16][4]) {
        #pragma unroll
        for (int j = 0; j < 16; j++)
            #pragma unroll
            for (int q = 0; q < 4; q++) acc[j][q] = 0.f;
    };
    auto repack_relu = [&](const float acc[16][4], const float* bias, u32 fr[8][4]) {
        #pragma unroll
        for (int tt = 0; tt < 8; tt++) {
            int c0 = tt * 16 + 2 * (lane & 3);
            float b0 = bias[c0], b1 = bias[c0 + 1];
            float b8 = bias[c0 + 8], b9 = bias[c0 + 9];
            fr[tt][0] = pack2(fmaxf(acc[2 * tt][0] + b0, 0.f),
                              fmaxf(acc[2 * tt][1] + b1, 0.f));
            fr[tt][1] = pack2(fmaxf(acc[2 * tt][2] + b0, 0.f),
                              fmaxf(acc[2 * tt][3] + b1, 0.f));
            fr[tt][2] = pack2(fmaxf(acc[2 * tt + 1][0] + b8, 0.f),
                              fmaxf(acc[2 * tt + 1][1] + b9, 0.f));
            fr[tt][3] = pack2(fmaxf(acc[2 * tt + 1][2] + b8, 0.f),
                              fmaxf(acc[2 * tt + 1][3] + b9, 0.f));
        }
    };

    stageA(x);
    loadW(0);
    if (tid < 128) {
        sB1[tid] = b1_rel[tid]; sB2[tid] = b2_rel[tid]; sBc[tid] = bc[tid];
        sBg1[tid] = bg1[tid]; sLg[tid] = lng[tid]; sLb[tid] = lnb[tid];
        sBg2[tid] = bg2[tid];
    }
    __syncthreads();

    u32 xf[8][4];
    ldA(xf);
    __syncthreads();

    float acc[16][4];

    // ---------- h1 ----------
    stageA(g_agg1);
    __syncthreads();
    u32 af[8][4];
    ldA(af);
    zacc(acc);
    gemmB(af, acc);
    __syncthreads();
    loadW(1);
    __syncthreads();
    gemmB(xf, acc);
    u32 h1f[8][4];
    repack_relu(acc, sB1, h1f);
    __syncthreads();

    // ---------- h2 ----------
    stageA(g_agg2);
    loadW(2);
    __syncthreads();
    ldA(af);
    zacc(acc);
    gemmB(af, acc);
    __syncthreads();
    loadW(3);
    __syncthreads();
    gemmB(xf, acc);
    u32 h2f[8][4];
    repack_relu(acc, sB2, h2f);
    __syncthreads();

    // ---------- h = relu(cat @ Wc + bc) ----------
    loadW(4);
    __syncthreads();
    zacc(acc);
    gemmB(h1f, acc);
    __syncthreads();
    loadW(5);
    __syncthreads();
    gemmB(h2f, acc);
    float hC[16][4];
    #pragma unroll
    for (int j = 0; j < 16; j++) {
        int c = j * 8 + 2 * (lane & 3);
        hC[j][0] = fmaxf(acc[j][0] + sBc[c],     0.f);
        hC[j][1] = fmaxf(acc[j][1] + sBc[c + 1], 0.f);
        hC[j][2] = fmaxf(acc[j][2] + sBc[c],     0.f);
        hC[j][3] = fmaxf(acc[j][3] + sBc[c + 1], 0.f);
    }
    __syncthreads();

    // ---------- g = (1+eps)*x + agg3 ----------
    {
        float epsv = 1.0f + *epsp;
        for (int i = tid; i < 128 * 32; i += 256) {
            int n = i >> 5, k4 = i & 31;
            int row = n0 + n;
            float4 xv = make_float4(0.f, 0.f, 0.f, 0.f);
            float4 av = make_float4(0.f, 0.f, 0.f, 0.f);
            if (row < NN) {
                xv = *(const float4*)(x + (size_t)row * HH + k4 * 4);
                av = *(const float4*)(g_agg3 + (size_t)row * HH + k4 * 4);
            }
            __half* dst = (__half*)(smraw + NOA) + n * 136 + k4 * 4;
            *(u32*)(dst)     = pack2(xv.x * epsv + av.x, xv.y * epsv + av.y);
            *(u32*)(dst + 2) = pack2(xv.z * epsv + av.z, xv.w * epsv + av.w);
        }
    }
    loadW(6);
    __syncthreads();

    // ---------- t = g @ Wg1 + bg1; LN; relu ----------
    ldA(af);
    zacc(acc);
    gemmB(af, acc);

    u32 tf[8][4];
    {
        float sA = 0.f, qA = 0.f, sBv = 0.f, qB = 0.f;
        #pragma unroll
        for (int j = 0; j < 16; j++) {
            int c = j * 8 + 2 * (lane & 3);
            acc[j][0] += sBg1[c];
            acc[j][1] += sBg1[c + 1];
            acc[j][2] += sBg1[c];
            acc[j][3] += sBg1[c + 1];
            sA += acc[j][0] + acc[j][1];
            qA += acc[j][0] * acc[j][0] + acc[j][1] * acc[j][1];
            sBv += acc[j][2] + acc[j][3];
            qB += acc[j][2] * acc[j][2] + acc[j][3] * acc[j][3];
        }
        #pragma unroll
        for (int d = 1; d < 4; d <<= 1) {
            sA  += __shfl_xor_sync(0xffffffffu, sA, d);
            qA  += __shfl_xor_sync(0xffffffffu, qA, d);
            sBv += __shfl_xor_sync(0xffffffffu, sBv, d);
            qB  += __shfl_xor_sync(0xffffffffu, qB, d);
        }
        float mA = sA * (1.f / 128.f);
        float vA = qA * (1.f / 128.f) - mA * mA;
        float rA = rsqrtf(vA + 1e-5f);
        float mB = sBv * (1.f / 128.f);
        float vB = qB * (1.f / 128.f) - mB * mB;
        float rB = rsqrtf(vB + 1e-5f);
        #pragma unroll
        for (int j = 0; j < 16; j++) {
            int c = j * 8 + 2 * (lane & 3);
            float g0 = sLg[c], g1 = sLg[c + 1], l0 = sLb[c], l1 = sLb[c + 1];
            acc[j][0] = fmaxf((acc[j][0] - mA) * rA * g0 + l0, 0.f);
            acc[j][1] = fmaxf((acc[j][1] - mA) * rA * g1 + l1, 0.f);
            acc[j][2] = fmaxf((acc[j][2] - mB) * rB * g0 + l0, 0.f);
            acc[j][3] = fmaxf((acc[j][3] - mB) * rB * g1 + l1, 0.f);
        }
        #pragma unroll
        for (int tt = 0; tt < 8; tt++) {
            tf[tt][0] = pack2(acc[2 * tt][0],     acc[2 * tt][1]);
            tf[tt][1] = pack2(acc[2 * tt][2],     acc[2 * tt][3]);
            tf[tt][2] = pack2(acc[2 * tt + 1][0], acc[2 * tt + 1][1]);
            tf[tt][3] = pack2(acc[2 * tt + 1][2], acc[2 * tt + 1][3]);
        }
    }
    __syncthreads();
    loadW(7);
    __syncthreads();

    // ---------- h3 = t @ Wg2 + bg2 ; out = h + h3 ----------
    zacc(acc);
    gemmB(tf, acc);
    {
        int r0 = n0 + 16 * w + (lane >> 2);
        int r1 = r0 + 8;
        #pragma unroll
        for (int j = 0; j < 16; j++) {
            int c = j * 8 + 2 * (lane & 3);
            float b0 = sBg2[c], b1 = sBg2[c + 1];
            if (r0 < NN) {
                float2 o = make_float2(hC[j][0] + acc[j][0] + b0,
                                       hC[j][1] + acc[j][1] + b1);
                *(float2*)(out + (size_t)r0 * HH + c) = o;
            }
            if (r1 < NN) {
                float2 o = make_float2(hC[j][2] + acc[j][2] + b0,
                                       hC[j][3] + acc[j][3] + b1);
                *(float2*)(out + (size_t)r1 * HH + c) = o;
            }
        }
    }
}

// ============================================================================
// Launch
// ============================================================================
extern "C" void kernel_launch(void* const* d_in, const int* in_sizes, int n_in,
                              void* d_out, int out_size)
{
    const float* x        = (const float*)d_in[0];
    const float* feature1 = (const float*)d_in[1];
    const float* feature2 = (const float*)d_in[2];
    const int *pei, *ei;
    const float* ea;
    if (in_sizes[3] == 2 * EE) {
        pei = (const int*)d_in[3]; ei = (const int*)d_in[4];
        ea  = (const float*)d_in[5];
    } else {
        ea  = (const float*)d_in[3];
        pei = (const int*)d_in[4]; ei = (const int*)d_in[5];
    }
    const float* Wf1a   = (const float*)d_in[6];
    const float* bf1a   = (const float*)d_in[7];
    const float* Wf1b   = (const float*)d_in[8];
    const float* bf1b   = (const float*)d_in[9];
    const float* Wf2a   = (const float*)d_in[10];
    const float* bf2a   = (const float*)d_in[11];
    const float* Wf2b   = (const float*)d_in[12];
    const float* bf2b   = (const float*)d_in[13];
    const float* W1_rel = (const float*)d_in[14];
    const float* b1_rel = (const float*)d_in[15];
    const float* W1_root= (const float*)d_in[16];
    const float* W2_rel = (const float*)d_in[17];
    const float* b2_rel = (const float*)d_in[18];
    const float* W2_root= (const float*)d_in[19];
    const float* epsp   = (const float*)d_in[20];
    const float* Wg1    = (const float*)d_in[21];
    const float* bg1    = (const float*)d_in[22];
    const float* lng    = (const float*)d_in[23];
    const float* lnb    = (const float*)d_in[24];
    const float* Wg2    = (const float*)d_in[25];
    const float* bg2    = (const float*)d_in[26];
    const float* Wc     = (const float*)d_in[27];
    const float* bc     = (const float*)d_in[28];
    float* out = (float*)d_out;

    float *agg1, *agg2, *agg3;
    __half *w1a, *w2a, *w1b, *w2b;
    cudaGetSymbolAddress((void**)&agg1, g_agg1);
    cudaGetSymbolAddress((void**)&agg2, g_agg2);
    cudaGetSymbolAddress((void**)&agg3, g_agg3);
    cudaGetSymbolAddress((void**)&w1a, g_W1aT);
    cudaGetSymbolAddress((void**)&w2a, g_W2aT);
    cudaGetSymbolAddress((void**)&w1b, g_W1bT);
    cudaGetSymbolAddress((void**)&w2b, g_W2bT);

    // smem: DK=128: 69632+67584+2*34816+1536+2048 = 210432
    //       DK=32 : 20480+67584+2*10240+34816+1536+2048 = 146944
    const int DYN128 = 210432;
    const int DYN32  = 146944;
    cudaFuncSetAttribute(edge_hmma<128>,
                         cudaFuncAttributeMaxDynamicSharedMemorySize, DYN128);
    cudaFuncSetAttribute(edge_hmma<32>,
                         cudaFuncAttributeMaxDynamicSharedMemorySize, DYN32);
    cudaFuncSetAttribute(node_hmma,
                         cudaFuncAttributeMaxDynamicSharedMemorySize, NODE_DYN);

    prep_weights<<<64, 256>>>(Wf1a, Wf1b, Wf2a, Wf2b,
                              W1_rel, W1_root, W2_rel, W2_root, Wc, Wg1, Wg2);

    cudaMemsetAsync(agg1, 0, sizeof(float) * NN * HH);
    cudaMemsetAsync(agg2, 0, sizeof(float) * NN * HH);
    cudaMemsetAsync(agg3, 0, sizeof(float) * NN * HH);

    // 4688 tiles of 128 edges, 8 per CTA -> 586 CTAs
    edge_hmma<128><<<586, 256, DYN128>>>(feature1, bf1a, bf1b, x, pei, agg1, w1a, w2a);
    edge_hmma<32><<<586, 256, DYN32>>>(feature2, bf2a, bf2b, x, pei, agg2, w1b, w2b);
    gine_scatter<<<EE / 8, 256>>>(x, ea, ei, agg3);

    node_hmma<<<(NN + 127) / 128, 256, NODE_DYN>>>(
        x, b1_rel, b2_rel, bc, epsp, bg1, lng, lnb, bg2, out);
}

// round 6
// speedup vs baseline: 4.6100x; 1.0113x over previous
#include <cuda_runtime.h>
#include <cuda_fp16.h>

#define NN 50000
#define EE 600000
#define HH 128
#define MIDD 256

typedef unsigned int u32;
typedef unsigned long long u64;

// ---------------- scratch (device globals) ----------------
__device__ float g_agg1[NN * HH];
__device__ float g_agg2[NN * HH];
__device__ float g_agg3[NN * HH];

// transposed padded fp16 weight images: [n][k] rows, padded strides
__device__ __align__(16) __half g_W1aT[256 * 136];  // Wf1a^T  (k=128, stride 136)
__device__ __align__(16) __half g_W2aT[128 * 264];  // Wf1b^T  (k=256, stride 264)
__device__ __align__(16) __half g_W1bT[256 * 40];   // Wf2a^T  (k=32,  stride 40)
__device__ __align__(16) __half g_W2bT[128 * 264];  // Wf2b^T  (k=256, stride 264)

// node weight images [128n][136k] fp16:
// 0:W1_rel 1:W1_root 2:W2_rel 3:W2_root 4:WcT1 5:WcT2 6:Wg1 7:Wg2
__device__ __align__(16) __half g_nW[8][128 * 136];

// ---------------- helpers ----------------
__device__ __forceinline__ u32 cvta_smem(const void* p) {
    u32 a;
    asm("{ .reg .u64 t; cvta.to.shared.u64 t, %1; cvt.u32.u64 %0, t; }"
        : "=r"(a) : "l"(p));
    return a;
}
__device__ __forceinline__ void ldm4(u32 r[4], u32 addr) {
    asm volatile("ldmatrix.sync.aligned.m8n8.x4.shared.b16 {%0,%1,%2,%3}, [%4];"
        : "=r"(r[0]), "=r"(r[1]), "=r"(r[2]), "=r"(r[3]) : "r"(addr));
}
__device__ __forceinline__ void mma16816(float c[4], const u32 a[4], u32 b0, u32 b1) {
    asm volatile(
        "mma.sync.aligned.m16n8k16.row.col.f32.f16.f16.f32 "
        "{%0,%1,%2,%3}, {%4,%5,%6,%7}, {%8,%9}, {%0,%1,%2,%3};"
        : "+f"(c[0]), "+f"(c[1]), "+f"(c[2]), "+f"(c[3])
        : "r"(a[0]), "r"(a[1]), "r"(a[2]), "r"(a[3]), "r"(b0), "r"(b1));
}
__device__ __forceinline__ u32 pack2(float x, float y) {
    __half2 h = __floats2half2_rn(x, y);
    return *(u32*)&h;
}
__device__ __forceinline__ void red4(float* p, float a, float b, float c, float d) {
    asm volatile("red.global.add.v4.f32 [%0], {%1, %2, %3, %4};"
                 :: "l"(p), "f"(a), "f"(b), "f"(c), "f"(d) : "memory");
}
#define CPA(dst, src) \
    asm volatile("cp.async.cg.shared.global [%0], [%1], 16;" \
                 :: "r"(dst), "l"(src) : "memory")
#define CPC() asm volatile("cp.async.commit_group;" ::: "memory")
#define CPW() asm volatile("cp.async.wait_group 0;" ::: "memory")

// ============================================================================
// Weight prep (unchanged).
// ============================================================================
__global__ void prep_weights(const float* __restrict__ Wf1a,
                             const float* __restrict__ Wf1b,
                             const float* __restrict__ Wf2a,
                             const float* __restrict__ Wf2b,
                             const float* __restrict__ W1_rel,
                             const float* __restrict__ W1_root,
                             const float* __restrict__ W2_rel,
                             const float* __restrict__ W2_root,
                             const float* __restrict__ Wc,
                             const float* __restrict__ Wg1,
                             const float* __restrict__ Wg2)
{
    int tid = blockIdx.x * blockDim.x + threadIdx.x;
    int nt = gridDim.x * blockDim.x;
    for (int i = tid; i < 256 * 128; i += nt) {
        int n = i >> 7, k = i & 127;
        g_W1aT[n * 136 + k] = __float2half(Wf1a[k * 256 + n]);
    }
    for (int i = tid; i < 128 * 256; i += nt) {
        int n = i >> 8, k = i & 255;
        g_W2aT[n * 264 + k] = __float2half(Wf1b[k * 128 + n]);
        g_W2bT[n * 264 + k] = __float2half(Wf2b[k * 128 + n]);
    }
    for (int i = tid; i < 256 * 32; i += nt) {
        int n = i >> 5, k = i & 31;
        g_W1bT[n * 40 + k] = __float2half(Wf2a[k * 256 + n]);
    }
    for (int i = tid; i < 128 * 128; i += nt) {
        int n = i >> 7, k = i & 127;
        g_nW[0][n * 136 + k] = __float2half(W1_rel[k * 128 + n]);
        g_nW[1][n * 136 + k] = __float2half(W1_root[k * 128 + n]);
        g_nW[2][n * 136 + k] = __float2half(W2_rel[k * 128 + n]);
        g_nW[3][n * 136 + k] = __float2half(W2_root[k * 128 + n]);
        g_nW[4][n * 136 + k] = __float2half(Wc[k * 128 + n]);
        g_nW[5][n * 136 + k] = __float2half(Wc[(k + 128) * 128 + n]);
        g_nW[6][n * 136 + k] = __float2half(Wg1[k * 128 + n]);
        g_nW[7][n * 136 + k] = __float2half(Wg2[k * 128 + n]);
    }
}

// ============================================================================
// Edge MLP via HMMA: 512 threads (16 warps), 256-edge tiles, 4 tiles/CTA.
// Single A buffer (F aliases A for DK=128); register prefetch across tiles.
// ============================================================================
#define ETILES 4

template<int DK>
__global__ __launch_bounds__(512, 1) void edge_hmma(
    const float* __restrict__ feat,
    const float* __restrict__ ba, const float* __restrict__ bb,
    const float* __restrict__ x, const int* __restrict__ eidx,
    float* __restrict__ agg,
    const __half* __restrict__ W1T, const __half* __restrict__ W2T)
{
    constexpr int SW1 = DK + 8;
    constexpr int W1SZ = 256 * SW1 * 2;
    constexpr int SW2 = 264;
    constexpr int W2SZ = 128 * SW2 * 2;
    constexpr int SA = DK + 8;
    constexpr int ASZ = 256 * SA * 2;
    constexpr int SF = 136;
    constexpr int OW1 = 0;
    constexpr int OW2 = OW1 + W1SZ;
    constexpr int OA  = OW2 + W2SZ;
    constexpr int OFS = OA + ASZ;
    constexpr int FSZ = (DK == 128) ? 0 : 256 * SF * 2;
    constexpr int OBA = OFS + FSZ;
    constexpr int OBB = OBA + 1024;
    constexpr int OIDX = OBB + 512;                   // int sIdx[512]
    constexpr int NKT = DK / 16;
    constexpr int DK4 = DK / 4;
    constexpr int LD = DK / 8;                        // float4 / thread / tile

    extern __shared__ unsigned char smraw[];
    const u32 sb = cvta_smem(smraw);
    const int tid = threadIdx.x;
    const int w = tid >> 5, lane = tid & 31;
    float* sBa = (float*)(smraw + OBA);
    float* sBb = (float*)(smraw + OBB);
    int* sIdx = (int*)(smraw + OIDX);

    // stage weights + biases (one-time)
    {
        const uint4* w1 = (const uint4*)W1T;
        const uint4* w2 = (const uint4*)W2T;
        uint4* s1 = (uint4*)(smraw + OW1);
        uint4* s2 = (uint4*)(smraw + OW2);
        for (int i = tid; i < W1SZ / 16; i += 512) s1[i] = w1[i];
        for (int i = tid; i < W2SZ / 16; i += 512) s2[i] = w2[i];
        if (tid < 256) sBa[tid] = ba[tid];
        else if (tid < 384) sBb[tid - 256] = bb[tid - 256];
    }

    u32 pf[2 * LD];
    int pfS = 0, pfD = 0;

    auto load_pf = [&](int t) {
        const int e0 = (blockIdx.x * ETILES + t) * 256;
        #pragma unroll
        for (int j = 0; j < LD; j++) {
            int i = tid + j * 512;
            int e = i / DK4, k4 = i % DK4;
            float4 v = make_float4(0.f, 0.f, 0.f, 0.f);
            if (e0 + e < EE) v = *(const float4*)(feat + (size_t)(e0 + e) * DK + k4 * 4);
            pf[2 * j]     = pack2(v.x, v.y);
            pf[2 * j + 1] = pack2(v.z, v.w);
        }
        if (tid < 256) {
            int e = e0 + tid;
            pfS = (e < EE) ? eidx[e] : 0;
            pfD = (e < EE) ? eidx[EE + e] : 0;
        }
    };
    auto store_pf = [&]() {
        __half* base = (__half*)(smraw + OA);
        #pragma unroll
        for (int j = 0; j < LD; j++) {
            int i = tid + j * 512;
            int e = i / DK4, k4 = i % DK4;
            *(uint2*)(base + e * SA + k4 * 4) = make_uint2(pf[2 * j], pf[2 * j + 1]);
        }
        if (tid < 256) {
            sIdx[tid] = pfS;
            sIdx[256 + tid] = pfD;
        }
    };

    load_pf(0);

    for (int t = 0; t < ETILES; t++) {
        const int e0 = (blockIdx.x * ETILES + t) * 256;
        store_pf();
        __syncthreads();                       // A + idx ready

        const u32 abase = sb + OA;
        u32 a1[NKT][4];
        #pragma unroll
        for (int kt = 0; kt < NKT; kt++)
            ldm4(a1[kt], abase + ((16 * w + (lane & 15)) * SA + kt * 16 + ((lane >> 4) << 3)) * 2);

        if (t + 1 < ETILES) load_pf(t + 1);    // overlap next DRAM with MMA

        float acc2[16][4];
        #pragma unroll
        for (int j = 0; j < 16; j++)
            #pragma unroll
            for (int q = 0; q < 4; q++) acc2[j][q] = 0.f;

        #pragma unroll
        for (int nc = 0; nc < 4; nc++) {
            float acc1[8][4];
            #pragma unroll
            for (int j = 0; j < 8; j++)
                #pragma unroll
                for (int q = 0; q < 4; q++) acc1[j][q] = 0.f;

            #pragma unroll
            for (int kt = 0; kt < NKT; kt++) {
                #pragma unroll
                for (int nn = 0; nn < 4; nn++) {
                    u32 b[4];
                    ldm4(b, sb + OW1 + ((nc * 64 + nn * 16 + (lane & 7) + ((lane >> 4) << 3)) * SW1
                                        + kt * 16 + (((lane >> 3) & 1) << 3)) * 2);
                    mma16816(acc1[2 * nn],     a1[kt], b[0], b[1]);
                    mma16816(acc1[2 * nn + 1], a1[kt], b[2], b[3]);
                }
            }
            u32 a2[4][4];
            #pragma unroll
            for (int tt = 0; tt < 4; tt++) {
                int c0 = nc * 64 + tt * 16 + 2 * (lane & 3);
                float b0 = sBa[c0], b1 = sBa[c0 + 1];
                float b8 = sBa[c0 + 8], b9 = sBa[c0 + 9];
                a2[tt][0] = pack2(fmaxf(acc1[2 * tt][0] + b0, 0.f),
                                  fmaxf(acc1[2 * tt][1] + b1, 0.f));
                a2[tt][1] = pack2(fmaxf(acc1[2 * tt][2] + b0, 0.f),
                                  fmaxf(acc1[2 * tt][3] + b1, 0.f));
                a2[tt][2] = pack2(fmaxf(acc1[2 * tt + 1][0] + b8, 0.f),
                                  fmaxf(acc1[2 * tt + 1][1] + b9, 0.f));
                a2[tt][3] = pack2(fmaxf(acc1[2 * tt + 1][2] + b8, 0.f),
                                  fmaxf(acc1[2 * tt + 1][3] + b9, 0.f));
            }
            #pragma unroll
            for (int tt = 0; tt < 4; tt++) {
                #pragma unroll
                for (int nn = 0; nn < 8; nn++) {
                    u32 b[4];
                    ldm4(b, sb + OW2 + ((nn * 16 + (lane & 7) + ((lane >> 4) << 3)) * SW2
                                        + nc * 64 + tt * 16 + (((lane >> 3) & 1) << 3)) * 2);
                    mma16816(acc2[2 * nn],     a2[tt], b[0], b[1]);
                    mma16816(acc2[2 * nn + 1], a2[tt], b[2], b[3]);
                }
            }
        }

        // f -> smem fp16 (aliases A for DK=128: per-warp row ownership, safe)
        __half* F = (DK == 128) ? (__half*)(smraw + OA) : (__half*)(smraw + OFS);
        {
            int row = 16 * w + (lane >> 2);
            #pragma unroll
            for (int j = 0; j < 16; j++) {
                int col = j * 8 + 2 * (lane & 3);
                *(u32*)(F + row * SF + col)       = pack2(acc2[j][0], acc2[j][1]);
                *(u32*)(F + (row + 8) * SF + col) = pack2(acc2[j][2], acc2[j][3]);
            }
        }
        __syncthreads();                       // F visible

        {
            int e = tid >> 1;
            int ch = (tid & 1) * 64;
            if (e0 + e < EE) {
                int src = sIdx[e], dst = sIdx[256 + e];
                const __half* Fr = F + e * SF + ch;
                const float4* xr = (const float4*)(x + (size_t)src * HH + ch);
                const float4* bbp = (const float4*)(sBb + ch);
                float* ap = agg + (size_t)dst * HH + ch;
                #pragma unroll
                for (int q = 0; q < 16; q++) {
                    float4 xv = __ldg(xr + q);
                    float4 bv = bbp[q];
                    float2 f0 = __half22float2(*(const __half2*)(Fr + q * 4));
                    float2 f1 = __half22float2(*(const __half2*)(Fr + q * 4 + 2));
                    red4(ap + q * 4,
                         (f0.x + bv.x) * xv.x, (f0.y + bv.y) * xv.y,
                         (f1.x + bv.z) * xv.z, (f1.y + bv.w) * xv.w);
                }
            }
        }
        __syncthreads();                       // scatter done before next store_pf
    }
}

// ============================================================================
// GINE scatter (unchanged).
// ============================================================================
__global__ __launch_bounds__(256) void gine_scatter(
    const float* __restrict__ x, const float* __restrict__ ea,
    const int* __restrict__ eidx, float* __restrict__ agg3)
{
    int e = blockIdx.x * 8 + (threadIdx.x >> 5);
    int lane = threadIdx.x & 31;
    int s = eidx[e];
    int d = eidx[EE + e];
    float4 v  = *(const float4*)(ea + (size_t)e * HH + lane * 4);
    float4 xv = *(const float4*)(x  + (size_t)s * HH + lane * 4);
    red4(agg3 + (size_t)d * HH + lane * 4, v.x + xv.x, v.y + xv.y, v.z + xv.z, v.w + xv.w);
}

// ============================================================================
// Node-level fused via HMMA, cp.async double-buffered weights.
// ============================================================================
#define NOA  0
#define NOW0 34816
#define NOW1 69632
#define NOB  104448
#define NODE_DYN 108032

__global__ __launch_bounds__(256, 1) void node_hmma(
    const float* __restrict__ x,
    const float* __restrict__ b1_rel, const float* __restrict__ b2_rel,
    const float* __restrict__ bc, const float* __restrict__ epsp,
    const float* __restrict__ bg1,
    const float* __restrict__ lng, const float* __restrict__ lnb,
    const float* __restrict__ bg2,
    float* __restrict__ out)
{
    extern __shared__ unsigned char smraw[];
    const u32 sb = cvta_smem(smraw);
    const int tid = threadIdx.x;
    const int w = tid >> 5, lane = tid & 31;
    const int n0 = blockIdx.x * 128;

    float* sB1 = (float*)(smraw + NOB);
    float* sB2 = sB1 + 128;
    float* sBc = sB2 + 128;
    float* sBg1 = sBc + 128;
    float* sLg = sBg1 + 128;
    float* sLb = sLg + 128;
    float* sBg2 = sLb + 128;

    auto stageA = [&](const float* src) {
        for (int i = tid; i < 128 * 32; i += 256) {
            int n = i >> 5, k4 = i & 31;
            int row = n0 + n;
            float4 v = make_float4(0.f, 0.f, 0.f, 0.f);
            if (row < NN) v = *(const float4*)(src + (size_t)row * HH + k4 * 4);
            __half* dst = (__half*)(smraw + NOA) + n * 136 + k4 * 4;
            *(u32*)(dst)     = pack2(v.x, v.y);
            *(u32*)(dst + 2) = pack2(v.z, v.w);
        }
    };
    auto loadW_async = [&](int wi, int buf) {
        const uint4* src = (const uint4*)g_nW[wi];
        u32 dst = sb + (buf ? NOW1 : NOW0);
        for (int i = tid; i < 2176; i += 256) CPA(dst + i * 16, src + i);
        CPC();
    };
    auto ldA = [&](u32 fr[8][4]) {
        #pragma unroll
        for (int kt = 0; kt < 8; kt++)
            ldm4(fr[kt], sb + NOA + ((16 * w + (lane & 15)) * 136 + kt * 16 + ((lane >> 4) << 3)) * 2);
    };
    auto gemmB = [&](const u32 fr[8][4], float acc[16][4], int buf) {
        const u32 wb = sb + (buf ? NOW1 : NOW0);
        #pragma unroll
        for (int kt = 0; kt < 8; kt++) {
            #pragma unroll
            for (int nn = 0; nn < 8; nn++) {
                u32 b[4];
                ldm4(b, wb + ((nn * 16 + (lane & 7) + ((lane >> 4) << 3)) * 136
                              + kt * 16 + (((lane >> 3) & 1) << 3)) * 2);
                mma16816(acc[2 * nn],     fr[kt], b[0], b[1]);
                mma16816(acc[2 * nn + 1], fr[kt], b[2], b[3]);
            }
        }
    };
    auto zacc = [&](float acc[16][4]) {
        #pragma unroll
        for (int j = 0; j < 16; j++)
            #pragma unroll
            for (int q = 0; q < 4; q++) acc[j][q] = 0.f;
    };
    auto repack_relu = [&](const float acc[16][4], const float* bias, u32 fr[8][4]) {
        #pragma unroll
        for (int tt = 0; tt < 8; tt++) {
            int c0 = tt * 16 + 2 * (lane & 3);
            float b0 = bias[c0], b1 = bias[c0 + 1];
            float b8 = bias[c0 + 8], b9 = bias[c0 + 9];
            fr[tt][0] = pack2(fmaxf(acc[2 * tt][0] + b0, 0.f),
                              fmaxf(acc[2 * tt][1] + b1, 0.f));
            fr[tt][1] = pack2(fmaxf(acc[2 * tt][2] + b0, 0.f),
                              fmaxf(acc[2 * tt][3] + b1, 0.f));
            fr[tt][2] = pack2(fmaxf(acc[2 * tt + 1][0] + b8, 0.f),
                              fmaxf(acc[2 * tt + 1][1] + b9, 0.f));
            fr[tt][3] = pack2(fmaxf(acc[2 * tt + 1][2] + b8, 0.f),
                              fmaxf(acc[2 * tt + 1][3] + b9, 0.f));
        }
    };

    // ---------- prologue: x stage + W0 async + biases ----------
    stageA(x);
    loadW_async(0, 0);
    if (tid < 128) {
        sB1[tid] = b1_rel[tid]; sB2[tid] = b2_rel[tid]; sBc[tid] = bc[tid];
        sBg1[tid] = bg1[tid]; sLg[tid] = lng[tid]; sLb[tid] = lnb[tid];
        sBg2[tid] = bg2[tid];
    }
    CPW();
    __syncthreads();

    u32 xf[8][4];
    ldA(xf);
    __syncthreads();                 // all warps read x before A reuse

    float acc[16][4];
    u32 af[8][4];

    // ---------- h1 ----------
    stageA(g_agg1);
    loadW_async(1, 1);
    __syncthreads();                 // A(agg1) ready; W0 ready since prologue
    ldA(af);
    zacc(acc);
    gemmB(af, acc, 0);               // agg1 @ W1_rel
    CPW();
    __syncthreads();                 // W1_root ready; b0 free
    loadW_async(2, 0);               // W2_rel -> b0
    gemmB(xf, acc, 1);               // + x @ W1_root
    u32 h1f[8][4];
    repack_relu(acc, sB1, h1f);
    stageA(g_agg2);
    CPW();
    __syncthreads();                 // W2_rel + A(agg2) ready; b1 free
    loadW_async(3, 1);               // W2_root -> b1

    // ---------- h2 ----------
    ldA(af);
    zacc(acc);
    gemmB(af, acc, 0);               // agg2 @ W2_rel
    CPW();
    __syncthreads();
    loadW_async(4, 0);               // Wc1 -> b0
    gemmB(xf, acc, 1);               // + x @ W2_root
    u32 h2f[8][4];
    repack_relu(acc, sB2, h2f);
    CPW();
    __syncthreads();
    loadW_async(5, 1);               // Wc2 -> b1

    // ---------- h = relu(cat @ Wc + bc) ----------
    zacc(acc);
    gemmB(h1f, acc, 0);
    CPW();
    __syncthreads();
    loadW_async(6, 0);               // Wg1 -> b0
    gemmB(h2f, acc, 1);
    float hC[16][4];
    #pragma unroll
    for (int j = 0; j < 16; j++) {
        int c = j * 8 + 2 * (lane & 3);
        hC[j][0] = fmaxf(acc[j][0] + sBc[c],     0.f);
        hC[j][1] = fmaxf(acc[j][1] + sBc[c + 1], 0.f);
        hC[j][2] = fmaxf(acc[j][2] + sBc[c],     0.f);
        hC[j][3] = fmaxf(acc[j][3] + sBc[c + 1], 0.f);
    }

    // ---------- g = (1+eps)*x + agg3 ----------
    {
        float epsv = 1.0f + *epsp;
        for (int i = tid; i < 128 * 32; i += 256) {
            int n = i >> 5, k4 = i & 31;
            int row = n0 + n;
            float4 xv = make_float4(0.f, 0.f, 0.f, 0.f);
            float4 av = make_float4(0.f, 0.f, 0.f, 0.f);
            if (row < NN) {
                xv = *(const float4*)(x + (size_t)row * HH + k4 * 4);
                av = *(const float4*)(g_agg3 + (size_t)row * HH + k4 * 4);
            }
            __half* dst = (__half*)(smraw + NOA) + n * 136 + k4 * 4;
            *(u32*)(dst)     = pack2(xv.x * epsv + av.x, xv.y * epsv + av.y);
            *(u32*)(dst + 2) = pack2(xv.z * epsv + av.z, xv.w * epsv + av.w);
        }
    }
    CPW();
    __syncthreads();                 // Wg1 + g ready; b1 free
    loadW_async(7, 1);               // Wg2 -> b1

    // ---------- t = g @ Wg1 + bg1; LN; relu ----------
    ldA(af);
    zacc(acc);
    gemmB(af, acc, 0);

    u32 tf[8][4];
    {
        float sA = 0.f, qA = 0.f, sBv = 0.f, qB = 0.f;
        #pragma unroll
        for (int j = 0; j < 16; j++) {
            int c = j * 8 + 2 * (lane & 3);
            acc[j][0] += sBg1[c];
            acc[j][1] += sBg1[c + 1];
            acc[j][2] += sBg1[c];
            acc[j][3] += sBg1[c + 1];
            sA += acc[j][0] + acc[j][1];
            qA += acc[j][0] * acc[j][0] + acc[j][1] * acc[j][1];
            sBv += acc[j][2] + acc[j][3];
            qB += acc[j][2] * acc[j][2] + acc[j][3] * acc[j][3];
        }
        #pragma unroll
        for (int d = 1; d < 4; d <<= 1) {
            sA  += __shfl_xor_sync(0xffffffffu, sA, d);
            qA  += __shfl_xor_sync(0xffffffffu, qA, d);
            sBv += __shfl_xor_sync(0xffffffffu, sBv, d);
            qB  += __shfl_xor_sync(0xffffffffu, qB, d);
        }
        float mA = sA * (1.f / 128.f);
        float vA = qA * (1.f / 128.f) - mA * mA;
        float rA = rsqrtf(vA + 1e-5f);
        float mB = sBv * (1.f / 128.f);
        float vB = qB * (1.f / 128.f) - mB * mB;
        float rB = rsqrtf(vB + 1e-5f);
        #pragma unroll
        for (int j = 0; j < 16; j++) {
            int c = j * 8 + 2 * (lane & 3);
            float g0 = sLg[c], g1 = sLg[c + 1], l0 = sLb[c], l1 = sLb[c + 1];
            acc[j][0] = fmaxf((acc[j][0] - mA) * rA * g0 + l0, 0.f);
            acc[j][1] = fmaxf((acc[j][1] - mA) * rA * g1 + l1, 0.f);
            acc[j][2] = fmaxf((acc[j][2] - mB) * rB * g0 + l0, 0.f);
            acc[j][3] = fmaxf((acc[j][3] - mB) * rB * g1 + l1, 0.f);
        }
        #pragma unroll
        for (int tt = 0; tt < 8; tt++) {
            tf[tt][0] = pack2(acc[2 * tt][0],     acc[2 * tt][1]);
            tf[tt][1] = pack2(acc[2 * tt][2],     acc[2 * tt][3]);
            tf[tt][2] = pack2(acc[2 * tt + 1][0], acc[2 * tt + 1][1]);
            tf[tt][3] = pack2(acc[2 * tt + 1][2], acc[2 * tt + 1][3]);
        }
    }
    CPW();
    __syncthreads();                 // Wg2 ready

    // ---------- h3 = t @ Wg2 + bg2 ; out = h + h3 ----------
    zacc(acc);
    gemmB(tf, acc, 1);
    {
        int r0 = n0 + 16 * w + (lane >> 2);
        int r1 = r0 + 8;
        #pragma unroll
        for (int j = 0; j < 16; j++) {
            int c = j * 8 + 2 * (lane & 3);
            float b0 = sBg2[c], b1 = sBg2[c + 1];
            if (r0 < NN) {
                float2 o = make_float2(hC[j][0] + acc[j][0] + b0,
                                       hC[j][1] + acc[j][1] + b1);
                *(float2*)(out + (size_t)r0 * HH + c) = o;
            }
            if (r1 < NN) {
                float2 o = make_float2(hC[j][2] + acc[j][2] + b0,
                                       hC[j][3] + acc[j][3] + b1);
                *(float2*)(out + (size_t)r1 * HH + c) = o;
            }
        }
    }
}

// ============================================================================
// Launch
// ============================================================================
extern "C" void kernel_launch(void* const* d_in, const int* in_sizes, int n_in,
                              void* d_out, int out_size)
{
    const float* x        = (const float*)d_in[0];
    const float* feature1 = (const float*)d_in[1];
    const float* feature2 = (const float*)d_in[2];
    const int *pei, *ei;
    const float* ea;
    if (in_sizes[3] == 2 * EE) {
        pei = (const int*)d_in[3]; ei = (const int*)d_in[4];
        ea  = (const float*)d_in[5];
    } else {
        ea  = (const float*)d_in[3];
        pei = (const int*)d_in[4]; ei = (const int*)d_in[5];
    }
    const float* Wf1a   = (const float*)d_in[6];
    const float* bf1a   = (const float*)d_in[7];
    const float* Wf1b   = (const float*)d_in[8];
    const float* bf1b   = (const float*)d_in[9];
    const float* Wf2a   = (const float*)d_in[10];
    const float* bf2a   = (const float*)d_in[11];
    const float* Wf2b   = (const float*)d_in[12];
    const float* bf2b   = (const float*)d_in[13];
    const float* W1_rel = (const float*)d_in[14];
    const float* b1_rel = (const float*)d_in[15];
    const float* W1_root= (const float*)d_in[16];
    const float* W2_rel = (const float*)d_in[17];
    const float* b2_rel = (const float*)d_in[18];
    const float* W2_root= (const float*)d_in[19];
    const float* epsp   = (const float*)d_in[20];
    const float* Wg1    = (const float*)d_in[21];
    const float* bg1    = (const float*)d_in[22];
    const float* lng    = (const float*)d_in[23];
    const float* lnb    = (const float*)d_in[24];
    const float* Wg2    = (const float*)d_in[25];
    const float* bg2    = (const float*)d_in[26];
    const float* Wc     = (const float*)d_in[27];
    const float* bc     = (const float*)d_in[28];
    float* out = (float*)d_out;

    float *agg1, *agg2, *agg3;
    __half *w1a, *w2a, *w1b, *w2b;
    cudaGetSymbolAddress((void**)&agg1, g_agg1);
    cudaGetSymbolAddress((void**)&agg2, g_agg2);
    cudaGetSymbolAddress((void**)&agg3, g_agg3);
    cudaGetSymbolAddress((void**)&w1a, g_W1aT);
    cudaGetSymbolAddress((void**)&w2a, g_W2aT);
    cudaGetSymbolAddress((void**)&w1b, g_W1bT);
    cudaGetSymbolAddress((void**)&w2b, g_W2bT);

    const int DYN128 = 210432;
    const int DYN32  = 181760;
    cudaFuncSetAttribute(edge_hmma<128>,
                         cudaFuncAttributeMaxDynamicSharedMemorySize, DYN128);
    cudaFuncSetAttribute(edge_hmma<32>,
                         cudaFuncAttributeMaxDynamicSharedMemorySize, DYN32);
    cudaFuncSetAttribute(node_hmma,
                         cudaFuncAttributeMaxDynamicSharedMemorySize, NODE_DYN);

    prep_weights<<<64, 256>>>(Wf1a, Wf1b, Wf2a, Wf2b,
                              W1_rel, W1_root, W2_rel, W2_root, Wc, Wg1, Wg2);

    cudaMemsetAsync(agg1, 0, sizeof(float) * NN * HH);
    cudaMemsetAsync(agg2, 0, sizeof(float) * NN * HH);
    cudaMemsetAsync(agg3, 0, sizeof(float) * NN * HH);

    // 2344 tiles of 256 edges, 4 per CTA -> 586 CTAs
    edge_hmma<128><<<586, 512, DYN128>>>(feature1, bf1a, bf1b, x, pei, agg1, w1a, w2a);
    edge_hmma<32><<<586, 512, DYN32>>>(feature2, bf2a, bf2b, x, pei, agg2, w1b, w2b);
    gine_scatter<<<EE / 8, 256>>>(x, ea, ei, agg3);

    node_hmma<<<(NN + 127) / 128, 256, NODE_DYN>>>(
        x, b1_rel, b2_rel, bc, epsp, bg1, lng, lnb, bg2, out);
}